// round 1
// baseline (speedup 1.0000x reference)
#include <cuda_runtime.h>
#include <math.h>

// ---------------- problem constants (fixed shapes) ----------------
#define HS    1024
#define NH    8
#define HD    128
#define BATCH 16
#define SEQ   2400
#define NBLK  200                  // ceil(SEQ/CHUNK), SEQ divisible
#define MROWS (BATCH*SEQ)          // 38400

#define CHUNKQ 12
#define PASTQ  12
#define CTXQ   24
#define PQ     25                  // CTX+1 rel positions

// Q_SCALE = 128^-0.5 / ln2 ; K_SCALE = ln(1+e)/ln2   (compile-time folded)
#define Q_SCALE_F (0.08838834764831845f / 0.6931471805599453f)
#define K_SCALE_F (1.3132616875182228f / 0.6931471805599453f)

// ---------------- scratch (device globals; no runtime alloc) ----------------
__device__ float g_q [(size_t)MROWS * HS];
__device__ float g_k [(size_t)MROWS * HS];
__device__ float g_v [(size_t)MROWS * HS];
__device__ float g_ao[(size_t)MROWS * HS];
__device__ float g_relk[PQ * HS];

// ---------------- SGEMM: C[M,N] = A[M,K] @ W[K,N], per-col epilogue scale ----
#define BM 128
#define BN 128
#define BKK 16

__device__ __forceinline__ void gemm_body(
    const float* __restrict__ A, const float* __restrict__ W,
    float* __restrict__ C, int K, int N,
    int scalemode, const float* __restrict__ pds, float cscale)
{
    __shared__ float As[2][BKK][BM];
    __shared__ float Bs[2][BKK][BN];
    const int t  = threadIdx.x;
    const int tx = t & 15, ty = t >> 4;
    const int m0 = blockIdx.y * BM;
    const int n0 = blockIdx.x * BN;

    const int arow = t >> 2;          // 0..63
    const int acol = (t & 3) * 4;     // 0,4,8,12
    const int brow = t >> 5;          // 0..7
    const int bcol = (t & 31) * 4;    // 0..124

    const float* Ap  = A + (size_t)(m0 + arow) * K + acol;
    const float* Ap2 = Ap + (size_t)64 * K;
    const float* Wp  = W + (size_t)brow * N + n0 + bcol;
    const float* Wp2 = Wp + (size_t)8 * N;

    float acc[8][8];
#pragma unroll
    for (int i = 0; i < 8; i++)
#pragma unroll
        for (int j = 0; j < 8; j++) acc[i][j] = 0.f;

    float4 a0 = *(const float4*)Ap;
    float4 a1 = *(const float4*)Ap2;
    float4 b0 = *(const float4*)Wp;
    float4 b1 = *(const float4*)Wp2;

    As[0][acol+0][arow]    = a0.x; As[0][acol+1][arow]    = a0.y;
    As[0][acol+2][arow]    = a0.z; As[0][acol+3][arow]    = a0.w;
    As[0][acol+0][arow+64] = a1.x; As[0][acol+1][arow+64] = a1.y;
    As[0][acol+2][arow+64] = a1.z; As[0][acol+3][arow+64] = a1.w;
    *(float4*)&Bs[0][brow  ][bcol] = b0;
    *(float4*)&Bs[0][brow+8][bcol] = b1;
    __syncthreads();

    int buf = 0;
    const int ntiles = K / BKK;
    for (int tile = 0; tile < ntiles; ++tile) {
        if (tile + 1 < ntiles) {
            const float* ap = Ap + (tile + 1) * BKK;
            a0 = *(const float4*)ap;
            a1 = *(const float4*)(ap + (size_t)64 * K);
            const float* wp = Wp + (size_t)(tile + 1) * BKK * N;
            b0 = *(const float4*)wp;
            b1 = *(const float4*)(wp + (size_t)8 * N);
        }
#pragma unroll
        for (int k = 0; k < BKK; k++) {
            float ar[8], br[8];
            *(float4*)&ar[0] = *(const float4*)&As[buf][k][ty*8];
            *(float4*)&ar[4] = *(const float4*)&As[buf][k][ty*8+4];
            *(float4*)&br[0] = *(const float4*)&Bs[buf][k][tx*8];
            *(float4*)&br[4] = *(const float4*)&Bs[buf][k][tx*8+4];
#pragma unroll
            for (int i = 0; i < 8; i++)
#pragma unroll
                for (int j = 0; j < 8; j++)
                    acc[i][j] = fmaf(ar[i], br[j], acc[i][j]);
        }
        if (tile + 1 < ntiles) {
            int nbuf = buf ^ 1;
            As[nbuf][acol+0][arow]    = a0.x; As[nbuf][acol+1][arow]    = a0.y;
            As[nbuf][acol+2][arow]    = a0.z; As[nbuf][acol+3][arow]    = a0.w;
            As[nbuf][acol+0][arow+64] = a1.x; As[nbuf][acol+1][arow+64] = a1.y;
            As[nbuf][acol+2][arow+64] = a1.z; As[nbuf][acol+3][arow+64] = a1.w;
            *(float4*)&Bs[nbuf][brow  ][bcol] = b0;
            *(float4*)&Bs[nbuf][brow+8][bcol] = b1;
            buf = nbuf;
        }
        __syncthreads();
    }

    float sc[8];
#pragma unroll
    for (int j = 0; j < 8; j++) {
        int col = n0 + tx * 8 + j;
        if (scalemode == 1) {
            float p  = pds[col & (HD - 1)];
            float sp = (p > 15.f) ? p : log1pf(expf(p));   // softplus
            sc[j] = Q_SCALE_F * sp;
        } else {
            sc[j] = cscale;
        }
    }
#pragma unroll
    for (int i = 0; i < 8; i++) {
        float* Cp = C + (size_t)(m0 + ty * 8 + i) * N + n0 + tx * 8;
        float4 v0, v1;
        v0.x = acc[i][0]*sc[0]; v0.y = acc[i][1]*sc[1];
        v0.z = acc[i][2]*sc[2]; v0.w = acc[i][3]*sc[3];
        v1.x = acc[i][4]*sc[4]; v1.y = acc[i][5]*sc[5];
        v1.z = acc[i][6]*sc[6]; v1.w = acc[i][7]*sc[7];
        *(float4*)Cp       = v0;
        *(float4*)(Cp + 4) = v1;
    }
}

__global__ __launch_bounds__(256, 2) void qkv_gemm(
    const float* __restrict__ x,
    const float* __restrict__ Wq, const float* __restrict__ Wk,
    const float* __restrict__ Wv, const float* __restrict__ pds)
{
    int z = blockIdx.z;
    if (z == 0)      gemm_body(x, Wq, g_q, HS, HS, 1, pds,  1.f);
    else if (z == 1) gemm_body(x, Wk, g_k, HS, HS, 0, 0, K_SCALE_F);
    else             gemm_body(x, Wv, g_v, HS, HS, 0, 0, 1.f);
}

__global__ __launch_bounds__(256, 2) void post_gemm(
    const float* __restrict__ Wpost, float* __restrict__ out)
{
    gemm_body(g_ao, Wpost, out, HS, HS, 0, 0, 1.f);
}

// ---------------- rel_k = pos_emb[25,1024] @ Wrel[1024,1024] ----------------
__global__ void relk_gemm(const float* __restrict__ pe, const float* __restrict__ Wrel)
{
    __shared__ float spe[PQ][256];
    const int t   = threadIdx.x;
    const int col = blockIdx.x * 256 + t;
    float acc[PQ];
#pragma unroll
    for (int p = 0; p < PQ; p++) acc[p] = 0.f;

    for (int k0 = 0; k0 < HS; k0 += 256) {
#pragma unroll
        for (int p = 0; p < PQ; p++) spe[p][t] = pe[p * HS + k0 + t];
        __syncthreads();
        for (int kk = 0; kk < 256; kk++) {
            float w = Wrel[(size_t)(k0 + kk) * HS + col];
#pragma unroll
            for (int p = 0; p < PQ; p++) acc[p] = fmaf(spe[p][kk], w, acc[p]);
        }
        __syncthreads();
    }
#pragma unroll
    for (int p = 0; p < PQ; p++) g_relk[p * HS + col] = acc[p];
}

// ---------------- blocked local attention core ----------------
// one block per (b, n, h); 128 threads
__global__ __launch_bounds__(128) void attn_kernel()
{
    const int bid = blockIdx.x;
    const int h = bid & 7;
    const int n = (bid >> 3) % NBLK;
    const int b = bid / (8 * NBLK);
    const int t = threadIdx.x;

    __shared__ float sq[CHUNKQ][HD];
    __shared__ float sk[CTXQ][HD];
    __shared__ float sv[CTXQ][HD];
    __shared__ float sr[PQ][HD];
    __shared__ float slog[CHUNKQ][CTXQ];
    __shared__ float sbd[CHUNKQ][PQ];

    const size_t base = (size_t)b * SEQ * HS + (size_t)h * HD;

    // load q chunk
    for (int f = t; f < CHUNKQ * 32; f += 128) {
        int i = f >> 5, c = (f & 31) << 2;
        int srow = n * CHUNKQ + i;
        float4 val = make_float4(0.f, 0.f, 0.f, 0.f);
        if (srow < SEQ) val = *(const float4*)&g_q[base + (size_t)srow * HS + c];
        *(float4*)&sq[i][c] = val;
    }
    // load k/v context (zero-padded left context at sequence start)
    for (int f = t; f < CTXQ * 32; f += 128) {
        int j = f >> 5, c = (f & 31) << 2;
        int s = n * CHUNKQ - PASTQ + j;
        float4 kv = make_float4(0.f, 0.f, 0.f, 0.f);
        float4 vv = make_float4(0.f, 0.f, 0.f, 0.f);
        if (s >= 0 && s < SEQ) {
            kv = *(const float4*)&g_k[base + (size_t)s * HS + c];
            vv = *(const float4*)&g_v[base + (size_t)s * HS + c];
        }
        *(float4*)&sk[j][c] = kv;
        *(float4*)&sv[j][c] = vv;
    }
    // load rel_k for this head
    for (int f = t; f < PQ * 32; f += 128) {
        int p = f >> 5, c = (f & 31) << 2;
        *(float4*)&sr[p][c] = *(const float4*)&g_relk[(size_t)p * HS + (size_t)h * HD + c];
    }
    __syncthreads();

    const int lane = t & 31;

    // content-content scores: ac[i][j] = q_i . k_j  (rotated-d indexing: conflict-free)
    for (int e = t; e < CHUNKQ * CTXQ; e += 128) {
        int i = e / CTXQ, j = e % CTXQ;
        float p0 = 0.f, p1 = 0.f, p2 = 0.f, p3 = 0.f;
#pragma unroll
        for (int u = 0; u < 32; u++) {
            int d = ((u + lane) & 31) << 2;
            float4 qa = *(const float4*)&sq[i][d];
            float4 ka = *(const float4*)&sk[j][d];
            p0 = fmaf(qa.x, ka.x, p0); p1 = fmaf(qa.y, ka.y, p1);
            p2 = fmaf(qa.z, ka.z, p2); p3 = fmaf(qa.w, ka.w, p3);
        }
        slog[i][j] = (p0 + p1) + (p2 + p3);
    }
    // content-position scores: bd[i][p] = q_i . relk_p
    for (int e = t; e < CHUNKQ * PQ; e += 128) {
        int i = e / PQ, p = e % PQ;
        float p0 = 0.f, p1 = 0.f, p2 = 0.f, p3 = 0.f;
#pragma unroll
        for (int u = 0; u < 32; u++) {
            int d = ((u + lane) & 31) << 2;
            float4 qa = *(const float4*)&sq[i][d];
            float4 ra = *(const float4*)&sr[p][d];
            p0 = fmaf(qa.x, ra.x, p0); p1 = fmaf(qa.y, ra.y, p1);
            p2 = fmaf(qa.z, ra.z, p2); p3 = fmaf(qa.w, ra.w, p3);
        }
        sbd[i][p] = (p0 + p1) + (p2 + p3);
    }
    __syncthreads();

    // rel-shift + softcap:  logit[i][j] = tanh((ac + bd[(i*24+j)/25][(i*24+j)%25])/50)*50
    for (int e = t; e < CHUNKQ * CTXQ; e += 128) {
        int i = e / CTXQ, j = e % CTXQ;
        float val = slog[i][j] + sbd[e / PQ][e % PQ];
        slog[i][j] = tanhf(val * (1.0f / 50.0f)) * 50.0f;
    }
    __syncthreads();

    // softmax per row (24 entries) — threads 0..11
    if (t < CHUNKQ) {
        float m = -1e30f;
#pragma unroll
        for (int j = 0; j < CTXQ; j++) m = fmaxf(m, slog[t][j]);
        float s = 0.f;
#pragma unroll
        for (int j = 0; j < CTXQ; j++) {
            float e = __expf(slog[t][j] - m);
            slog[t][j] = e;
            s += e;
        }
        float inv = 1.0f / s;
#pragma unroll
        for (int j = 0; j < CTXQ; j++) slog[t][j] *= inv;
    }
    __syncthreads();

    // out[i][d] = sum_j attn[i][j] * v[j][d]   (d = tid, conflict-free)
    {
        const int d = t;
#pragma unroll
        for (int i = 0; i < CHUNKQ; i++) {
            float a0 = 0.f, a1 = 0.f;
#pragma unroll
            for (int j = 0; j < CTXQ; j += 2) {
                a0 = fmaf(slog[i][j],     sv[j][d],     a0);
                a1 = fmaf(slog[i][j + 1], sv[j + 1][d], a1);
            }
            int srow = n * CHUNKQ + i;
            if (srow < SEQ) g_ao[base + (size_t)srow * HS + d] = a0 + a1;
        }
    }
}

// ---------------- launch ----------------
extern "C" void kernel_launch(void* const* d_in, const int* in_sizes, int n_in,
                              void* d_out, int out_size)
{
    const float* x     = (const float*)d_in[0];
    const float* pe    = (const float*)d_in[1];
    const float* Wq    = (const float*)d_in[2];
    const float* Wk    = (const float*)d_in[3];
    const float* Wv    = (const float*)d_in[4];
    const float* Wpost = (const float*)d_in[5];
    const float* Wrel  = (const float*)d_in[6];
    const float* pds   = (const float*)d_in[7];
    float* out = (float*)d_out;

    // rel_k projection (tiny)
    relk_gemm<<<HS / 256, 256>>>(pe, Wrel);

    // fused QKV projections with epilogue scaling
    dim3 gq(HS / BN, MROWS / BM, 3);
    qkv_gemm<<<gq, 256>>>(x, Wq, Wk, Wv, pds);

    // blocked local attention
    attn_kernel<<<BATCH * NBLK * NH, 128>>>();

    // output projection
    dim3 gp(HS / BN, MROWS / BM);
    post_gemm<<<gp, 256>>>(Wpost, out);
}

// round 2
// speedup vs baseline: 2.2988x; 2.2988x over previous
#include <cuda_runtime.h>
#include <math.h>

// ---------------- problem constants (fixed shapes) ----------------
#define HS    1024
#define NH    8
#define HD    128
#define BATCH 16
#define SEQ   2400
#define NBLK  200
#define MROWS (BATCH*SEQ)          // 38400

#define CHUNKQ 12
#define PASTQ  12
#define CTXQ   24
#define PQ     25

#define Q_SCALE_F (0.08838834764831845f / 0.6931471805599453f)
#define K_SCALE_F (1.3132616875182228f / 0.6931471805599453f)

// ---------------- scratch ----------------
__device__ float g_q [(size_t)MROWS * HS];
__device__ float g_k [(size_t)MROWS * HS];
__device__ float g_v [(size_t)MROWS * HS];
__device__ float g_ao[(size_t)MROWS * HS];
__device__ float g_relk[PQ * HS];

// ---------------- tf32 tensor-core GEMM ----------------
// C[M,1024] = A[M,1024] @ W[1024,1024]; BM=128, BN=128, BK=16
// 256 threads = 8 warps; warp tile 64(m) x 32(n) via m16n8k8 tf32 mma.

#define BM 128
#define BN 128
#define BK 16
#define APAD 4     // As[BM][BK+APAD]
#define BPAD 4     // Bs[BK][BN+BPAD]
#define KTILES (HS / BK)

__device__ __forceinline__ unsigned cvta_smem(const void* p) {
    return (unsigned)__cvta_generic_to_shared(p);
}
__device__ __forceinline__ void cp_async16(void* dst, const void* src) {
    asm volatile("cp.async.cg.shared.global [%0], [%1], 16;\n"
                 :: "r"(cvta_smem(dst)), "l"(src));
}
__device__ __forceinline__ void cp_commit() {
    asm volatile("cp.async.commit_group;\n");
}
__device__ __forceinline__ unsigned f2tf32(float f) {
    unsigned r;
    asm("cvt.rna.tf32.f32 %0, %1;\n" : "=r"(r) : "f"(f));
    return r;
}
__device__ __forceinline__ void mma1688(float* d, unsigned a0, unsigned a1,
                                        unsigned a2, unsigned a3,
                                        unsigned b0, unsigned b1) {
    asm volatile(
        "mma.sync.aligned.m16n8k8.row.col.f32.tf32.tf32.f32 "
        "{%0,%1,%2,%3}, {%4,%5,%6,%7}, {%8,%9}, {%0,%1,%2,%3};\n"
        : "+f"(d[0]), "+f"(d[1]), "+f"(d[2]), "+f"(d[3])
        : "r"(a0), "r"(a1), "r"(a2), "r"(a3), "r"(b0), "r"(b1));
}

__device__ __forceinline__ void gemm_tf32(
    const float* __restrict__ A, const float* __restrict__ W,
    float* __restrict__ C,
    int scalemode, const float* __restrict__ pds, float cscale)
{
    __shared__ float As[2][BM][BK + APAD];
    __shared__ float Bs[2][BK][BN + BPAD];

    const int t    = threadIdx.x;
    const int lane = t & 31;
    const int warp = t >> 5;
    const int wrow = (warp & 1) * 64;   // warp m-offset
    const int wcol = (warp >> 1) * 32;  // warp n-offset
    const int g    = lane >> 2;         // group id 0..7
    const int tg   = lane & 3;          // thread-in-group 0..3

    const int m0 = blockIdx.y * BM;
    const int n0 = blockIdx.x * BN;

    // cp.async tile loaders: A 512 float4, B 512 float4; 2 each per thread
    const int ar0 = t >> 2,        ac0 = (t & 3) * 4;       // idx = t
    const int ar1 = (t + 256) >> 2, ac1 = ac0;              // idx = t+256
    const int br0 = t >> 5,        bc0 = (t & 31) * 4;
    const int br1 = (t + 256) >> 5, bc1 = bc0;

    const float* Abase = A + (size_t)m0 * HS;
    const float* Wbase = W + n0;

    float acc[4][4][4];
#pragma unroll
    for (int i = 0; i < 4; i++)
#pragma unroll
        for (int j = 0; j < 4; j++)
#pragma unroll
            for (int c = 0; c < 4; c++) acc[i][j][c] = 0.f;

    // preload tile 0
    {
        const float* ap = Abase;  // k0 = 0
        cp_async16(&As[0][ar0][ac0], ap + (size_t)ar0 * HS + ac0);
        cp_async16(&As[0][ar1][ac1], ap + (size_t)ar1 * HS + ac1);
        cp_async16(&Bs[0][br0][bc0], Wbase + (size_t)br0 * HS + bc0);
        cp_async16(&Bs[0][br1][bc1], Wbase + (size_t)br1 * HS + bc1);
        cp_commit();
    }

    for (int tile = 0; tile < KTILES; ++tile) {
        const int buf = tile & 1;
        if (tile + 1 < KTILES) {
            const int nb = buf ^ 1;
            const int k0 = (tile + 1) * BK;
            const float* ap = Abase + k0;
            const float* wp = Wbase + (size_t)k0 * HS;
            cp_async16(&As[nb][ar0][ac0], ap + (size_t)ar0 * HS + ac0);
            cp_async16(&As[nb][ar1][ac1], ap + (size_t)ar1 * HS + ac1);
            cp_async16(&Bs[nb][br0][bc0], wp + (size_t)br0 * HS + bc0);
            cp_async16(&Bs[nb][br1][bc1], wp + (size_t)br1 * HS + bc1);
            cp_commit();
            asm volatile("cp.async.wait_group 1;\n");
        } else {
            asm volatile("cp.async.wait_group 0;\n");
        }
        __syncthreads();

#pragma unroll
        for (int kk = 0; kk < 2; kk++) {
            const int k = kk * 8;
            unsigned af[4][4], bf[4][2];
#pragma unroll
            for (int mt = 0; mt < 4; mt++) {
                int r = wrow + mt * 16 + g;
                af[mt][0] = f2tf32(As[buf][r    ][k + tg]);
                af[mt][1] = f2tf32(As[buf][r + 8][k + tg]);
                af[mt][2] = f2tf32(As[buf][r    ][k + 4 + tg]);
                af[mt][3] = f2tf32(As[buf][r + 8][k + 4 + tg]);
            }
#pragma unroll
            for (int nt = 0; nt < 4; nt++) {
                int cn = wcol + nt * 8 + g;
                bf[nt][0] = f2tf32(Bs[buf][k + tg    ][cn]);
                bf[nt][1] = f2tf32(Bs[buf][k + 4 + tg][cn]);
            }
#pragma unroll
            for (int mt = 0; mt < 4; mt++)
#pragma unroll
                for (int nt = 0; nt < 4; nt++)
                    mma1688(acc[mt][nt], af[mt][0], af[mt][1], af[mt][2],
                            af[mt][3], bf[nt][0], bf[nt][1]);
        }
        __syncthreads();
    }

    // epilogue: per-column scale, write C
    float sc[4][2];
#pragma unroll
    for (int nt = 0; nt < 4; nt++) {
#pragma unroll
        for (int ci = 0; ci < 2; ci++) {
            int col = n0 + wcol + nt * 8 + tg * 2 + ci;
            if (scalemode == 1) {
                float p  = pds[col & (HD - 1)];
                float sp = (p > 15.f) ? p : log1pf(expf(p));
                sc[nt][ci] = Q_SCALE_F * sp;
            } else {
                sc[nt][ci] = cscale;
            }
        }
    }
#pragma unroll
    for (int mt = 0; mt < 4; mt++) {
#pragma unroll
        for (int half = 0; half < 2; half++) {
            int row = m0 + wrow + mt * 16 + half * 8 + g;
            float* Cp = C + (size_t)row * HS + n0 + wcol;
#pragma unroll
            for (int nt = 0; nt < 4; nt++) {
                float2 v;
                v.x = acc[mt][nt][half * 2 + 0] * sc[nt][0];
                v.y = acc[mt][nt][half * 2 + 1] * sc[nt][1];
                *(float2*)(Cp + nt * 8 + tg * 2) = v;
            }
        }
    }
}

__global__ __launch_bounds__(256, 2) void qkv_gemm(
    const float* __restrict__ x,
    const float* __restrict__ Wq, const float* __restrict__ Wk,
    const float* __restrict__ Wv, const float* __restrict__ pds)
{
    int z = blockIdx.z;
    if (z == 0)      gemm_tf32(x, Wq, g_q, 1, pds,  1.f);
    else if (z == 1) gemm_tf32(x, Wk, g_k, 0, 0, K_SCALE_F);
    else             gemm_tf32(x, Wv, g_v, 0, 0, 1.f);
}

__global__ __launch_bounds__(256, 2) void post_gemm(
    const float* __restrict__ Wpost, float* __restrict__ out)
{
    gemm_tf32(g_ao, Wpost, out, 0, 0, 1.f);
}

// ---------------- rel_k = pos_emb[25,1024] @ Wrel[1024,1024] (fp32) --------
__global__ void relk_gemm(const float* __restrict__ pe, const float* __restrict__ Wrel)
{
    __shared__ float spe[PQ][256];
    const int t   = threadIdx.x;
    const int col = blockIdx.x * 256 + t;
    float acc[PQ];
#pragma unroll
    for (int p = 0; p < PQ; p++) acc[p] = 0.f;

    for (int k0 = 0; k0 < HS; k0 += 256) {
#pragma unroll
        for (int p = 0; p < PQ; p++) spe[p][t] = pe[p * HS + k0 + t];
        __syncthreads();
        for (int kk = 0; kk < 256; kk++) {
            float w = Wrel[(size_t)(k0 + kk) * HS + col];
#pragma unroll
            for (int p = 0; p < PQ; p++) acc[p] = fmaf(spe[p][kk], w, acc[p]);
        }
        __syncthreads();
    }
#pragma unroll
    for (int p = 0; p < PQ; p++) g_relk[p * HS + col] = acc[p];
}

// ---------------- blocked local attention core ----------------
__global__ __launch_bounds__(128) void attn_kernel()
{
    const int bid = blockIdx.x;
    const int h = bid & 7;
    const int n = (bid >> 3) % NBLK;
    const int b = bid / (8 * NBLK);
    const int t = threadIdx.x;

    __shared__ float sq[CHUNKQ][HD];
    __shared__ float sk[CTXQ][HD];
    __shared__ float sv[CTXQ][HD];
    __shared__ float sr[PQ][HD];
    __shared__ float slog[CHUNKQ][CTXQ];
    __shared__ float sbd[CHUNKQ][PQ];

    const size_t base = (size_t)b * SEQ * HS + (size_t)h * HD;

    for (int f = t; f < CHUNKQ * 32; f += 128) {
        int i = f >> 5, c = (f & 31) << 2;
        int srow = n * CHUNKQ + i;
        float4 val = make_float4(0.f, 0.f, 0.f, 0.f);
        if (srow < SEQ) val = *(const float4*)&g_q[base + (size_t)srow * HS + c];
        *(float4*)&sq[i][c] = val;
    }
    for (int f = t; f < CTXQ * 32; f += 128) {
        int j = f >> 5, c = (f & 31) << 2;
        int s = n * CHUNKQ - PASTQ + j;
        float4 kv = make_float4(0.f, 0.f, 0.f, 0.f);
        float4 vv = make_float4(0.f, 0.f, 0.f, 0.f);
        if (s >= 0 && s < SEQ) {
            kv = *(const float4*)&g_k[base + (size_t)s * HS + c];
            vv = *(const float4*)&g_v[base + (size_t)s * HS + c];
        }
        *(float4*)&sk[j][c] = kv;
        *(float4*)&sv[j][c] = vv;
    }
    for (int f = t; f < PQ * 32; f += 128) {
        int p = f >> 5, c = (f & 31) << 2;
        *(float4*)&sr[p][c] = *(const float4*)&g_relk[(size_t)p * HS + (size_t)h * HD + c];
    }
    __syncthreads();

    const int lane = t & 31;

    for (int e = t; e < CHUNKQ * CTXQ; e += 128) {
        int i = e / CTXQ, j = e % CTXQ;
        float p0 = 0.f, p1 = 0.f, p2 = 0.f, p3 = 0.f;
#pragma unroll
        for (int u = 0; u < 32; u++) {
            int d = ((u + lane) & 31) << 2;
            float4 qa = *(const float4*)&sq[i][d];
            float4 ka = *(const float4*)&sk[j][d];
            p0 = fmaf(qa.x, ka.x, p0); p1 = fmaf(qa.y, ka.y, p1);
            p2 = fmaf(qa.z, ka.z, p2); p3 = fmaf(qa.w, ka.w, p3);
        }
        slog[i][j] = (p0 + p1) + (p2 + p3);
    }
    for (int e = t; e < CHUNKQ * PQ; e += 128) {
        int i = e / PQ, p = e % PQ;
        float p0 = 0.f, p1 = 0.f, p2 = 0.f, p3 = 0.f;
#pragma unroll
        for (int u = 0; u < 32; u++) {
            int d = ((u + lane) & 31) << 2;
            float4 qa = *(const float4*)&sq[i][d];
            float4 ra = *(const float4*)&sr[p][d];
            p0 = fmaf(qa.x, ra.x, p0); p1 = fmaf(qa.y, ra.y, p1);
            p2 = fmaf(qa.z, ra.z, p2); p3 = fmaf(qa.w, ra.w, p3);
        }
        sbd[i][p] = (p0 + p1) + (p2 + p3);
    }
    __syncthreads();

    for (int e = t; e < CHUNKQ * CTXQ; e += 128) {
        int i = e / CTXQ, j = e % CTXQ;
        float val = slog[i][j] + sbd[e / PQ][e % PQ];
        slog[i][j] = tanhf(val * (1.0f / 50.0f)) * 50.0f;
    }
    __syncthreads();

    if (t < CHUNKQ) {
        float m = -1e30f;
#pragma unroll
        for (int j = 0; j < CTXQ; j++) m = fmaxf(m, slog[t][j]);
        float s = 0.f;
#pragma unroll
        for (int j = 0; j < CTXQ; j++) {
            float e = __expf(slog[t][j] - m);
            slog[t][j] = e;
            s += e;
        }
        float inv = 1.0f / s;
#pragma unroll
        for (int j = 0; j < CTXQ; j++) slog[t][j] *= inv;
    }
    __syncthreads();

    {
        const int d = t;
#pragma unroll
        for (int i = 0; i < CHUNKQ; i++) {
            float a0 = 0.f, a1 = 0.f;
#pragma unroll
            for (int j = 0; j < CTXQ; j += 2) {
                a0 = fmaf(slog[i][j],     sv[j][d],     a0);
                a1 = fmaf(slog[i][j + 1], sv[j + 1][d], a1);
            }
            int srow = n * CHUNKQ + i;
            if (srow < SEQ) g_ao[base + (size_t)srow * HS + d] = a0 + a1;
        }
    }
}

// ---------------- launch ----------------
extern "C" void kernel_launch(void* const* d_in, const int* in_sizes, int n_in,
                              void* d_out, int out_size)
{
    const float* x     = (const float*)d_in[0];
    const float* pe    = (const float*)d_in[1];
    const float* Wq    = (const float*)d_in[2];
    const float* Wk    = (const float*)d_in[3];
    const float* Wv    = (const float*)d_in[4];
    const float* Wpost = (const float*)d_in[5];
    const float* Wrel  = (const float*)d_in[6];
    const float* pds   = (const float*)d_in[7];
    float* out = (float*)d_out;

    relk_gemm<<<HS / 256, 256>>>(pe, Wrel);

    dim3 gq(HS / BN, MROWS / BM, 3);
    qkv_gemm<<<gq, 256>>>(x, Wq, Wk, Wv, pds);

    attn_kernel<<<BATCH * NBLK * NH, 128>>>();

    dim3 gp(HS / BN, MROWS / BM);
    post_gemm<<<gp, 256>>>(Wpost, out);
}

// round 3
// speedup vs baseline: 2.7273x; 1.1864x over previous
#include <cuda_runtime.h>
#include <math.h>

// ---------------- problem constants ----------------
#define HS    1024
#define NH    8
#define HD    128
#define BATCH 16
#define SEQ   2400
#define NBLK  200
#define MROWS (BATCH*SEQ)          // 38400

#define CHUNKQ 12
#define PASTQ  12
#define CTXQ   24
#define PQ     25

#define Q_SCALE_F (0.08838834764831845f / 0.6931471805599453f)
#define K_SCALE_F (1.3132616875182228f / 0.6931471805599453f)

// ---------------- scratch ----------------
__device__ float g_q  [(size_t)MROWS * HS];
__device__ float g_k  [(size_t)MROWS * HS];
__device__ float g_v  [(size_t)MROWS * HS];
__device__ float g_ao [(size_t)MROWS * HS];   // attn out, tf32-rounded at store
__device__ float g_xr [(size_t)MROWS * HS];   // x, tf32-rounded
__device__ float g_wt [4][(size_t)HS * HS];   // transposed+rounded Wq,Wk,Wv,Wpost
__device__ float g_relk[PQ * HS];

__device__ __forceinline__ unsigned cvta_smem(const void* p) {
    return (unsigned)__cvta_generic_to_shared(p);
}
__device__ __forceinline__ void cp_async16(void* dst, const void* src) {
    asm volatile("cp.async.cg.shared.global [%0], [%1], 16;\n"
                 :: "r"(cvta_smem(dst)), "l"(src));
}
__device__ __forceinline__ void cp_commit() {
    asm volatile("cp.async.commit_group;\n");
}
__device__ __forceinline__ float roundtf32(float f) {
    unsigned r;
    asm("cvt.rna.tf32.f32 %0, %1;\n" : "=r"(r) : "f"(f));
    return __uint_as_float(r);
}
__device__ __forceinline__ void mma1688(float* d, unsigned a0, unsigned a1,
                                        unsigned a2, unsigned a3,
                                        unsigned b0, unsigned b1) {
    asm volatile(
        "mma.sync.aligned.m16n8k8.row.col.f32.tf32.tf32.f32 "
        "{%0,%1,%2,%3}, {%4,%5,%6,%7}, {%8,%9}, {%0,%1,%2,%3};\n"
        : "+f"(d[0]), "+f"(d[1]), "+f"(d[2]), "+f"(d[3])
        : "r"(a0), "r"(a1), "r"(a2), "r"(a3), "r"(b0), "r"(b1));
}

// ---------------- prep kernels ----------------
__global__ __launch_bounds__(256) void prep_x(const float* __restrict__ x)
{
    size_t i = ((size_t)blockIdx.x * 256 + threadIdx.x) * 4;
    float4 v = *(const float4*)(x + i);
    v.x = roundtf32(v.x); v.y = roundtf32(v.y);
    v.z = roundtf32(v.z); v.w = roundtf32(v.w);
    *(float4*)(g_xr + i) = v;
}

// transpose + round: g_wt[z][n][k] = round(W[k][n])
__global__ __launch_bounds__(256) void prep_w(
    const float* __restrict__ Wq, const float* __restrict__ Wk,
    const float* __restrict__ Wv, const float* __restrict__ Wpost)
{
    __shared__ float tile[32][33];
    const float* src = (blockIdx.z == 0) ? Wq : (blockIdx.z == 1) ? Wk
                     : (blockIdx.z == 2) ? Wv : Wpost;
    const int tx = threadIdx.x, ty = threadIdx.y;   // 32 x 8
    const int x0 = blockIdx.x * 32, y0 = blockIdx.y * 32;
#pragma unroll
    for (int i = 0; i < 32; i += 8)
        tile[ty + i][tx] = src[(size_t)(y0 + ty + i) * HS + x0 + tx];
    __syncthreads();
    float* dst = g_wt[blockIdx.z];
#pragma unroll
    for (int i = 0; i < 32; i += 8)
        dst[(size_t)(x0 + ty + i) * HS + y0 + tx] = roundtf32(tile[tx][ty + i]);
}

// ---------------- tf32 tensor-core GEMM ----------------
// A is tf32-rounded [M][K], Wt is tf32-rounded [N][K]. BM=BN=128, BK=16.
#define BM 128
#define BN 128
#define BK 16
#define KTILES (HS / BK)

__device__ __forceinline__ void gemm_tf32(
    const float* __restrict__ A, const float* __restrict__ Wt,
    float* __restrict__ C,
    int scalemode, const float* __restrict__ pds, float cscale)
{
    __shared__ float As[2][BM][BK];   // [row][k], conflict-free (verified)
    __shared__ float Bs[2][BN][BK];   // [col][k]

    const int t    = threadIdx.x;
    const int lane = t & 31;
    const int warp = t >> 5;
    const int wrow = (warp & 1) * 64;
    const int wcol = (warp >> 1) * 32;
    const int g    = lane >> 2;
    const int tg   = lane & 3;

    const int m0 = blockIdx.y * BM;
    const int n0 = blockIdx.x * BN;

    // loaders: 512 16B chunks per tile per operand; 2 per thread
    const int r0c = t >> 2,         c0c = (t & 3) * 4;
    const int r1c = (t + 256) >> 2, c1c = c0c;

    const float* Abase = A  + (size_t)m0 * HS;
    const float* Bbase = Wt + (size_t)n0 * HS;

    float acc[4][4][4];
#pragma unroll
    for (int i = 0; i < 4; i++)
#pragma unroll
        for (int j = 0; j < 4; j++)
#pragma unroll
            for (int c = 0; c < 4; c++) acc[i][j][c] = 0.f;

    cp_async16(&As[0][r0c][c0c], Abase + (size_t)r0c * HS + c0c);
    cp_async16(&As[0][r1c][c1c], Abase + (size_t)r1c * HS + c1c);
    cp_async16(&Bs[0][r0c][c0c], Bbase + (size_t)r0c * HS + c0c);
    cp_async16(&Bs[0][r1c][c1c], Bbase + (size_t)r1c * HS + c1c);
    cp_commit();

    for (int tile = 0; tile < KTILES; ++tile) {
        const int buf = tile & 1;
        if (tile + 1 < KTILES) {
            const int nb = buf ^ 1;
            const int k0 = (tile + 1) * BK;
            const float* ap = Abase + k0;
            const float* bp = Bbase + k0;
            cp_async16(&As[nb][r0c][c0c], ap + (size_t)r0c * HS + c0c);
            cp_async16(&As[nb][r1c][c1c], ap + (size_t)r1c * HS + c1c);
            cp_async16(&Bs[nb][r0c][c0c], bp + (size_t)r0c * HS + c0c);
            cp_async16(&Bs[nb][r1c][c1c], bp + (size_t)r1c * HS + c1c);
            cp_commit();
            asm volatile("cp.async.wait_group 1;\n");
        } else {
            asm volatile("cp.async.wait_group 0;\n");
        }
        __syncthreads();

        // fragments: one float4 covers logical k = 4tg..4tg+3
        uint4 alo[4], ahi[4], bfr[4];
#pragma unroll
        for (int mt = 0; mt < 4; mt++) {
            int r = wrow + mt * 16 + g;
            alo[mt] = *(const uint4*)&As[buf][r    ][4 * tg];
            ahi[mt] = *(const uint4*)&As[buf][r + 8][4 * tg];
        }
#pragma unroll
        for (int nt = 0; nt < 4; nt++) {
            int cn = wcol + nt * 8 + g;
            bfr[nt] = *(const uint4*)&Bs[buf][cn][4 * tg];
        }
        // kk0: slots use k=4tg+0 (lo) and 4tg+1 (hi); kk1: 4tg+2 / 4tg+3
#pragma unroll
        for (int mt = 0; mt < 4; mt++)
#pragma unroll
            for (int nt = 0; nt < 4; nt++)
                mma1688(acc[mt][nt], alo[mt].x, ahi[mt].x, alo[mt].y, ahi[mt].y,
                        bfr[nt].x, bfr[nt].y);
#pragma unroll
        for (int mt = 0; mt < 4; mt++)
#pragma unroll
            for (int nt = 0; nt < 4; nt++)
                mma1688(acc[mt][nt], alo[mt].z, ahi[mt].z, alo[mt].w, ahi[mt].w,
                        bfr[nt].z, bfr[nt].w);
        __syncthreads();
    }

    // epilogue
    float sc[4][2];
#pragma unroll
    for (int nt = 0; nt < 4; nt++) {
#pragma unroll
        for (int ci = 0; ci < 2; ci++) {
            int col = n0 + wcol + nt * 8 + tg * 2 + ci;
            if (scalemode == 1) {
                float p  = pds[col & (HD - 1)];
                float sp = (p > 15.f) ? p : log1pf(expf(p));
                sc[nt][ci] = Q_SCALE_F * sp;
            } else {
                sc[nt][ci] = cscale;
            }
        }
    }
#pragma unroll
    for (int mt = 0; mt < 4; mt++) {
#pragma unroll
        for (int half = 0; half < 2; half++) {
            int row = m0 + wrow + mt * 16 + half * 8 + g;
            float* Cp = C + (size_t)row * HS + n0 + wcol;
#pragma unroll
            for (int nt = 0; nt < 4; nt++) {
                float2 v;
                v.x = acc[mt][nt][half * 2 + 0] * sc[nt][0];
                v.y = acc[mt][nt][half * 2 + 1] * sc[nt][1];
                *(float2*)(Cp + nt * 8 + tg * 2) = v;
            }
        }
    }
}

__global__ __launch_bounds__(256, 2) void qkv_gemm(const float* __restrict__ pds)
{
    int z = blockIdx.z;
    if (z == 0)      gemm_tf32(g_xr, g_wt[0], g_q, 1, pds,  1.f);
    else if (z == 1) gemm_tf32(g_xr, g_wt[1], g_k, 0, 0, K_SCALE_F);
    else             gemm_tf32(g_xr, g_wt[2], g_v, 0, 0, 1.f);
}

__global__ __launch_bounds__(256, 2) void post_gemm(float* __restrict__ out)
{
    gemm_tf32(g_ao, g_wt[3], out, 0, 0, 1.f);
}

// ---------------- rel_k = pos_emb[25,1024] @ Wrel (fp32, k-split) ----------
__global__ void relk_zero()
{
    g_relk[blockIdx.x * 1024 + threadIdx.x] = 0.f;
}

__global__ __launch_bounds__(128) void relk_gemm(
    const float* __restrict__ pe, const float* __restrict__ Wrel)
{
    __shared__ float spe[PQ][256];
    const int t   = threadIdx.x;
    const int col = blockIdx.x * 128 + t;
    const int k0  = blockIdx.y * 256;

    for (int f = t; f < PQ * 256; f += 128) {
        int p = f >> 8, kk = f & 255;
        spe[p][kk] = pe[p * HS + k0 + kk];
    }
    __syncthreads();

    float acc[PQ];
#pragma unroll
    for (int p = 0; p < PQ; p++) acc[p] = 0.f;
    for (int kk = 0; kk < 256; kk++) {
        float w = Wrel[(size_t)(k0 + kk) * HS + col];
#pragma unroll
        for (int p = 0; p < PQ; p++) acc[p] = fmaf(spe[p][kk], w, acc[p]);
    }
#pragma unroll
    for (int p = 0; p < PQ; p++) atomicAdd(&g_relk[p * HS + col], acc[p]);
}

// ---------------- blocked local attention core ----------------
__global__ __launch_bounds__(128) void attn_kernel()
{
    const int bid = blockIdx.x;
    const int h = bid & 7;
    const int n = (bid >> 3) % NBLK;
    const int b = bid / (8 * NBLK);
    const int t = threadIdx.x;

    __shared__ float sq[CHUNKQ][HD];
    __shared__ float sk[CTXQ][HD];
    __shared__ float sv[CTXQ][HD];
    __shared__ float sr[PQ][HD];
    __shared__ float slog[CHUNKQ][CTXQ];
    __shared__ float sbd[CHUNKQ][PQ];

    const size_t base = (size_t)b * SEQ * HS + (size_t)h * HD;

    for (int f = t; f < CHUNKQ * 32; f += 128) {
        int i = f >> 5, c = (f & 31) << 2;
        int srow = n * CHUNKQ + i;
        float4 val = make_float4(0.f, 0.f, 0.f, 0.f);
        if (srow < SEQ) val = *(const float4*)&g_q[base + (size_t)srow * HS + c];
        *(float4*)&sq[i][c] = val;
    }
    for (int f = t; f < CTXQ * 32; f += 128) {
        int j = f >> 5, c = (f & 31) << 2;
        int s = n * CHUNKQ - PASTQ + j;
        float4 kv = make_float4(0.f, 0.f, 0.f, 0.f);
        float4 vv = make_float4(0.f, 0.f, 0.f, 0.f);
        if (s >= 0 && s < SEQ) {
            kv = *(const float4*)&g_k[base + (size_t)s * HS + c];
            vv = *(const float4*)&g_v[base + (size_t)s * HS + c];
        }
        *(float4*)&sk[j][c] = kv;
        *(float4*)&sv[j][c] = vv;
    }
    for (int f = t; f < PQ * 32; f += 128) {
        int p = f >> 5, c = (f & 31) << 2;
        *(float4*)&sr[p][c] = *(const float4*)&g_relk[(size_t)p * HS + (size_t)h * HD + c];
    }
    __syncthreads();

    const int lane = t & 31;

    for (int e = t; e < CHUNKQ * CTXQ; e += 128) {
        int i = e / CTXQ, j = e % CTXQ;
        float p0 = 0.f, p1 = 0.f, p2 = 0.f, p3 = 0.f;
#pragma unroll
        for (int u = 0; u < 32; u++) {
            int d = ((u + lane) & 31) << 2;
            float4 qa = *(const float4*)&sq[i][d];
            float4 ka = *(const float4*)&sk[j][d];
            p0 = fmaf(qa.x, ka.x, p0); p1 = fmaf(qa.y, ka.y, p1);
            p2 = fmaf(qa.z, ka.z, p2); p3 = fmaf(qa.w, ka.w, p3);
        }
        slog[i][j] = (p0 + p1) + (p2 + p3);
    }
    for (int e = t; e < CHUNKQ * PQ; e += 128) {
        int i = e / PQ, p = e % PQ;
        float p0 = 0.f, p1 = 0.f, p2 = 0.f, p3 = 0.f;
#pragma unroll
        for (int u = 0; u < 32; u++) {
            int d = ((u + lane) & 31) << 2;
            float4 qa = *(const float4*)&sq[i][d];
            float4 ra = *(const float4*)&sr[p][d];
            p0 = fmaf(qa.x, ra.x, p0); p1 = fmaf(qa.y, ra.y, p1);
            p2 = fmaf(qa.z, ra.z, p2); p3 = fmaf(qa.w, ra.w, p3);
        }
        sbd[i][p] = (p0 + p1) + (p2 + p3);
    }
    __syncthreads();

    for (int e = t; e < CHUNKQ * CTXQ; e += 128) {
        int i = e / CTXQ, j = e % CTXQ;
        float val = slog[i][j] + sbd[e / PQ][e % PQ];
        slog[i][j] = tanhf(val * (1.0f / 50.0f)) * 50.0f;
    }
    __syncthreads();

    if (t < CHUNKQ) {
        float m = -1e30f;
#pragma unroll
        for (int j = 0; j < CTXQ; j++) m = fmaxf(m, slog[t][j]);
        float s = 0.f;
#pragma unroll
        for (int j = 0; j < CTXQ; j++) {
            float e = __expf(slog[t][j] - m);
            slog[t][j] = e;
            s += e;
        }
        float inv = 1.0f / s;
#pragma unroll
        for (int j = 0; j < CTXQ; j++) slog[t][j] *= inv;
    }
    __syncthreads();

    {
        const int d = t;
#pragma unroll
        for (int i = 0; i < CHUNKQ; i++) {
            float a0 = 0.f, a1 = 0.f;
#pragma unroll
            for (int j = 0; j < CTXQ; j += 2) {
                a0 = fmaf(slog[i][j],     sv[j][d],     a0);
                a1 = fmaf(slog[i][j + 1], sv[j + 1][d], a1);
            }
            int srow = n * CHUNKQ + i;
            if (srow < SEQ)
                g_ao[base + (size_t)srow * HS + d] = roundtf32(a0 + a1);
        }
    }
}

// ---------------- launch ----------------
extern "C" void kernel_launch(void* const* d_in, const int* in_sizes, int n_in,
                              void* d_out, int out_size)
{
    const float* x     = (const float*)d_in[0];
    const float* pe    = (const float*)d_in[1];
    const float* Wq    = (const float*)d_in[2];
    const float* Wk    = (const float*)d_in[3];
    const float* Wv    = (const float*)d_in[4];
    const float* Wpost = (const float*)d_in[5];
    const float* Wrel  = (const float*)d_in[6];
    const float* pds   = (const float*)d_in[7];
    float* out = (float*)d_out;

    prep_x<<<(size_t)MROWS * HS / 4 / 256, 256>>>(x);
    prep_w<<<dim3(32, 32, 4), dim3(32, 8)>>>(Wq, Wk, Wv, Wpost);

    relk_zero<<<PQ, 1024>>>();
    relk_gemm<<<dim3(8, 4), 128>>>(pe, Wrel);

    dim3 gq(HS / BN, MROWS / BM, 3);
    qkv_gemm<<<gq, 256>>>(pds);

    attn_kernel<<<BATCH * NBLK * NH, 128>>>();

    dim3 gp(HS / BN, MROWS / BM);
    post_gemm<<<gp, 256>>>(out);
}

// round 4
// speedup vs baseline: 4.3522x; 1.5958x over previous
#include <cuda_runtime.h>
#include <cuda_fp16.h>
#include <math.h>

// ---------------- problem constants ----------------
#define HS    1024
#define NH    8
#define HD    128
#define BATCH 16
#define SEQ   2400
#define NBLK  200
#define MROWS (BATCH*SEQ)          // 38400

#define CHUNKQ 12
#define PASTQ  12
#define CTXQ   24
#define PQ     25

#define Q_SCALE_F (0.08838834764831845f / 0.6931471805599453f)
#define K_SCALE_F (1.3132616875182228f / 0.6931471805599453f)

// ---------------- scratch ----------------
__device__ float  g_q  [(size_t)MROWS * HS];
__device__ float  g_k  [(size_t)MROWS * HS];
__device__ float  g_v  [(size_t)MROWS * HS];
__device__ __half g_aoh[(size_t)MROWS * HS];     // attn out (half)
__device__ __half g_xh [(size_t)MROWS * HS];     // x (half)
__device__ __half g_wth[4][(size_t)HS * HS];     // W^T (half): q,k,v,post
__device__ float  g_relk[PQ * HS];

__device__ __forceinline__ unsigned cvta_smem(const void* p) {
    return (unsigned)__cvta_generic_to_shared(p);
}
__device__ __forceinline__ void cp_async16(void* dst, const void* src) {
    asm volatile("cp.async.cg.shared.global [%0], [%1], 16;\n"
                 :: "r"(cvta_smem(dst)), "l"(src));
}
__device__ __forceinline__ void cp_commit() {
    asm volatile("cp.async.commit_group;\n");
}
__device__ __forceinline__ void ldm_x4(unsigned& r0, unsigned& r1,
                                       unsigned& r2, unsigned& r3, unsigned a) {
    asm volatile("ldmatrix.sync.aligned.m8n8.x4.shared.b16 {%0,%1,%2,%3}, [%4];\n"
                 : "=r"(r0), "=r"(r1), "=r"(r2), "=r"(r3) : "r"(a));
}
__device__ __forceinline__ void mma16816(float* d, unsigned a0, unsigned a1,
                                         unsigned a2, unsigned a3,
                                         unsigned b0, unsigned b1) {
    asm volatile(
        "mma.sync.aligned.m16n8k16.row.col.f32.f16.f16.f32 "
        "{%0,%1,%2,%3}, {%4,%5,%6,%7}, {%8,%9}, {%0,%1,%2,%3};\n"
        : "+f"(d[0]), "+f"(d[1]), "+f"(d[2]), "+f"(d[3])
        : "r"(a0), "r"(a1), "r"(a2), "r"(a3), "r"(b0), "r"(b1));
}

// ---------------- prep ----------------
// x -> half; first 100 blocks also zero g_relk
__global__ __launch_bounds__(256) void prep_xh(const float* __restrict__ x)
{
    if (blockIdx.x < 100) g_relk[blockIdx.x * 256 + threadIdx.x] = 0.f;
    size_t i = ((size_t)blockIdx.x * 256 + threadIdx.x) * 4;
    float4 v = *(const float4*)(x + i);
    __half2 h0 = __floats2half2_rn(v.x, v.y);
    __half2 h1 = __floats2half2_rn(v.z, v.w);
    *(__half2*)(g_xh + i)     = h0;
    *(__half2*)(g_xh + i + 2) = h1;
}

// transpose + half: g_wth[z][n][k] = (half)W[k][n]
__global__ __launch_bounds__(256) void prep_wh(
    const float* __restrict__ Wq, const float* __restrict__ Wk,
    const float* __restrict__ Wv, const float* __restrict__ Wpost)
{
    __shared__ float tile[32][33];
    const float* src = (blockIdx.z == 0) ? Wq : (blockIdx.z == 1) ? Wk
                     : (blockIdx.z == 2) ? Wv : Wpost;
    const int tx = threadIdx.x, ty = threadIdx.y;   // 32 x 8
    const int x0 = blockIdx.x * 32, y0 = blockIdx.y * 32;
#pragma unroll
    for (int i = 0; i < 32; i += 8)
        tile[ty + i][tx] = src[(size_t)(y0 + ty + i) * HS + x0 + tx];
    __syncthreads();
    __half* dst = g_wth[blockIdx.z];
#pragma unroll
    for (int i = 0; i < 32; i += 8)
        dst[(size_t)(x0 + ty + i) * HS + y0 + tx] = __float2half(tile[tx][ty + i]);
}

// ---------------- fp16 tensor-core GEMM ----------------
// A half [M][K], Wt half [N][K]; BM=BN=128, BK=32 halfs; 256 thr, warp 64x32
#define BM 128
#define BN 128
#define BKH 32
#define BKP 40                     // padded row: 80B => conflict-free ldmatrix
#define KTILES (HS / BKH)
#define SMEM_GEMM_BYTES (2 * 2 * 128 * BKP * 2)   // As+Bs, 2 bufs: 40960

__device__ __forceinline__ void gemm_fp16(
    const __half* __restrict__ A, const __half* __restrict__ Wt,
    float* __restrict__ C,
    int scalemode, const float* __restrict__ pds, float cscale, void* pool)
{
    __half* As = (__half*)pool;              // [2][128][BKP]
    __half* Bs = As + 2 * 128 * BKP;         // [2][128][BKP]

    const int t    = threadIdx.x;
    const int lane = t & 31;
    const int warp = t >> 5;
    const int wrow = (warp & 1) * 64;
    const int wcol = (warp >> 1) * 32;
    const int g    = lane >> 2;
    const int tg   = lane & 3;

    const int m0 = blockIdx.y * BM;
    const int n0 = blockIdx.x * BN;

    // loaders: 128 rows x 4 chunks(16B) = 512 chunks per operand; 2/thread
    const int r0c = t >> 2,         c0c = (t & 3) * 8;
    const int r1c = (t + 256) >> 2, c1c = c0c;

    const __half* Abase = A  + (size_t)m0 * HS;
    const __half* Bbase = Wt + (size_t)n0 * HS;

    // ldmatrix address components
    const int aRow = (lane & 7) + ((lane >> 3) & 1) * 8;
    const int aCol = ((lane >> 4) & 1) * 8;
    const int bRow = (lane & 7) + ((lane >> 4) & 1) * 8;
    const int bCol = ((lane >> 3) & 1) * 8;

    float acc[4][4][4];
#pragma unroll
    for (int i = 0; i < 4; i++)
#pragma unroll
        for (int j = 0; j < 4; j++)
#pragma unroll
            for (int c = 0; c < 4; c++) acc[i][j][c] = 0.f;

    cp_async16(As + (size_t)r0c * BKP + c0c, Abase + (size_t)r0c * HS + c0c);
    cp_async16(As + (size_t)r1c * BKP + c1c, Abase + (size_t)r1c * HS + c1c);
    cp_async16(Bs + (size_t)r0c * BKP + c0c, Bbase + (size_t)r0c * HS + c0c);
    cp_async16(Bs + (size_t)r1c * BKP + c1c, Bbase + (size_t)r1c * HS + c1c);
    cp_commit();

    for (int tile = 0; tile < KTILES; ++tile) {
        const int buf = tile & 1;
        const int bo  = buf * 128 * BKP;
        if (tile + 1 < KTILES) {
            const int nb = (buf ^ 1) * 128 * BKP;
            const int k0 = (tile + 1) * BKH;
            const __half* ap = Abase + k0;
            const __half* bp = Bbase + k0;
            cp_async16(As + nb + (size_t)r0c * BKP + c0c, ap + (size_t)r0c * HS + c0c);
            cp_async16(As + nb + (size_t)r1c * BKP + c1c, ap + (size_t)r1c * HS + c1c);
            cp_async16(Bs + nb + (size_t)r0c * BKP + c0c, bp + (size_t)r0c * HS + c0c);
            cp_async16(Bs + nb + (size_t)r1c * BKP + c1c, bp + (size_t)r1c * HS + c1c);
            cp_commit();
            asm volatile("cp.async.wait_group 1;\n");
        } else {
            asm volatile("cp.async.wait_group 0;\n");
        }
        __syncthreads();

#pragma unroll
        for (int kk = 0; kk < 2; kk++) {
            const int kh = kk * 16;
            unsigned af[4][4], bf[4][2];
#pragma unroll
            for (int mt = 0; mt < 4; mt++) {
                unsigned a = cvta_smem(As + bo +
                    (size_t)(wrow + mt * 16 + aRow) * BKP + kh + aCol);
                ldm_x4(af[mt][0], af[mt][1], af[mt][2], af[mt][3], a);
            }
#pragma unroll
            for (int p = 0; p < 2; p++) {
                unsigned a = cvta_smem(Bs + bo +
                    (size_t)(wcol + p * 16 + bRow) * BKP + kh + bCol);
                ldm_x4(bf[2*p][0], bf[2*p][1], bf[2*p+1][0], bf[2*p+1][1], a);
            }
#pragma unroll
            for (int mt = 0; mt < 4; mt++)
#pragma unroll
                for (int nt = 0; nt < 4; nt++)
                    mma16816(acc[mt][nt], af[mt][0], af[mt][1], af[mt][2],
                             af[mt][3], bf[nt][0], bf[nt][1]);
        }
        __syncthreads();
    }

    // epilogue
    float sc[4][2];
#pragma unroll
    for (int nt = 0; nt < 4; nt++) {
#pragma unroll
        for (int ci = 0; ci < 2; ci++) {
            int col = n0 + wcol + nt * 8 + tg * 2 + ci;
            if (scalemode == 1) {
                float p  = pds[col & (HD - 1)];
                float sp = (p > 15.f) ? p : log1pf(expf(p));
                sc[nt][ci] = Q_SCALE_F * sp;
            } else {
                sc[nt][ci] = cscale;
            }
        }
    }
#pragma unroll
    for (int mt = 0; mt < 4; mt++) {
#pragma unroll
        for (int half = 0; half < 2; half++) {
            int row = m0 + wrow + mt * 16 + half * 8 + g;
            float* Cp = C + (size_t)row * HS + n0 + wcol;
#pragma unroll
            for (int nt = 0; nt < 4; nt++) {
                float2 v;
                v.x = acc[mt][nt][half * 2 + 0] * sc[nt][0];
                v.y = acc[mt][nt][half * 2 + 1] * sc[nt][1];
                *(float2*)(Cp + nt * 8 + tg * 2) = v;
            }
        }
    }
}

// relk partial (runs inside qkv_gemm z==3): 8 col-groups x 4 k-splits
__device__ __forceinline__ void relk_body(
    const float* __restrict__ pe, const float* __restrict__ Wrel, void* pool)
{
    float* spe = (float*)pool;                 // [25][256]
    const int t = threadIdx.x;                 // 256 threads
    const int col = blockIdx.x * 128 + (t & 127);
    const int k0  = blockIdx.y * 256;
    const int kh  = (t >> 7) * 128;

    for (int f = t; f < PQ * 256; f += 256)
        spe[f] = pe[(f >> 8) * HS + k0 + (f & 255)];
    __syncthreads();

    float acc[PQ];
#pragma unroll
    for (int p = 0; p < PQ; p++) acc[p] = 0.f;
    for (int kk = 0; kk < 128; kk++) {
        float w = Wrel[(size_t)(k0 + kh + kk) * HS + col];
#pragma unroll
        for (int p = 0; p < PQ; p++) acc[p] = fmaf(spe[p * 256 + kh + kk], w, acc[p]);
    }
#pragma unroll
    for (int p = 0; p < PQ; p++) atomicAdd(&g_relk[p * HS + col], acc[p]);
}

__global__ __launch_bounds__(256, 2) void qkv_gemm(
    const float* __restrict__ pds,
    const float* __restrict__ pe, const float* __restrict__ Wrel)
{
    __shared__ __align__(16) unsigned char pool[SMEM_GEMM_BYTES];
    int z = blockIdx.z;
    if (z == 3) {
        if (blockIdx.y < 4 && blockIdx.x < 8) relk_body(pe, Wrel, pool);
        return;
    }
    if (z == 0)      gemm_fp16(g_xh, g_wth[0], g_q, 1, pds,  1.f, pool);
    else if (z == 1) gemm_fp16(g_xh, g_wth[1], g_k, 0, 0, K_SCALE_F, pool);
    else             gemm_fp16(g_xh, g_wth[2], g_v, 0, 0, 1.f, pool);
}

__global__ __launch_bounds__(256, 2) void post_gemm(float* __restrict__ out)
{
    __shared__ __align__(16) unsigned char pool[SMEM_GEMM_BYTES];
    gemm_fp16(g_aoh, g_wth[3], out, 0, 0, 1.f, pool);
}

// ---------------- blocked local attention core ----------------
__global__ __launch_bounds__(128) void attn_kernel()
{
    const int bid = blockIdx.x;
    const int h = bid & 7;
    const int n = (bid >> 3) % NBLK;
    const int b = bid / (8 * NBLK);
    const int t = threadIdx.x;

    __shared__ float sq[CHUNKQ][HD];
    __shared__ float sk[CTXQ][HD];
    __shared__ float sv[CTXQ][HD];
    __shared__ float sr[PQ][HD];
    __shared__ float slog[CHUNKQ][CTXQ];
    __shared__ float sbd[CHUNKQ][PQ];

    const size_t base = (size_t)b * SEQ * HS + (size_t)h * HD;

    for (int f = t; f < CHUNKQ * 32; f += 128) {
        int i = f >> 5, c = (f & 31) << 2;
        int srow = n * CHUNKQ + i;
        float4 val = make_float4(0.f, 0.f, 0.f, 0.f);
        if (srow < SEQ) val = *(const float4*)&g_q[base + (size_t)srow * HS + c];
        *(float4*)&sq[i][c] = val;
    }
    for (int f = t; f < CTXQ * 32; f += 128) {
        int j = f >> 5, c = (f & 31) << 2;
        int s = n * CHUNKQ - PASTQ + j;
        float4 kv = make_float4(0.f, 0.f, 0.f, 0.f);
        float4 vv = make_float4(0.f, 0.f, 0.f, 0.f);
        if (s >= 0 && s < SEQ) {
            kv = *(const float4*)&g_k[base + (size_t)s * HS + c];
            vv = *(const float4*)&g_v[base + (size_t)s * HS + c];
        }
        *(float4*)&sk[j][c] = kv;
        *(float4*)&sv[j][c] = vv;
    }
    for (int f = t; f < PQ * 32; f += 128) {
        int p = f >> 5, c = (f & 31) << 2;
        *(float4*)&sr[p][c] = *(const float4*)&g_relk[(size_t)p * HS + (size_t)h * HD + c];
    }
    __syncthreads();

    const int lane = t & 31;

    for (int e = t; e < CHUNKQ * CTXQ; e += 128) {
        int i = e / CTXQ, j = e % CTXQ;
        float p0 = 0.f, p1 = 0.f, p2 = 0.f, p3 = 0.f;
#pragma unroll
        for (int u = 0; u < 32; u++) {
            int d = ((u + lane) & 31) << 2;
            float4 qa = *(const float4*)&sq[i][d];
            float4 ka = *(const float4*)&sk[j][d];
            p0 = fmaf(qa.x, ka.x, p0); p1 = fmaf(qa.y, ka.y, p1);
            p2 = fmaf(qa.z, ka.z, p2); p3 = fmaf(qa.w, ka.w, p3);
        }
        slog[i][j] = (p0 + p1) + (p2 + p3);
    }
    for (int e = t; e < CHUNKQ * PQ; e += 128) {
        int i = e / PQ, p = e % PQ;
        float p0 = 0.f, p1 = 0.f, p2 = 0.f, p3 = 0.f;
#pragma unroll
        for (int u = 0; u < 32; u++) {
            int d = ((u + lane) & 31) << 2;
            float4 qa = *(const float4*)&sq[i][d];
            float4 ra = *(const float4*)&sr[p][d];
            p0 = fmaf(qa.x, ra.x, p0); p1 = fmaf(qa.y, ra.y, p1);
            p2 = fmaf(qa.z, ra.z, p2); p3 = fmaf(qa.w, ra.w, p3);
        }
        sbd[i][p] = (p0 + p1) + (p2 + p3);
    }
    __syncthreads();

    for (int e = t; e < CHUNKQ * CTXQ; e += 128) {
        int i = e / CTXQ, j = e % CTXQ;
        float val = slog[i][j] + sbd[e / PQ][e % PQ];
        slog[i][j] = tanhf(val * (1.0f / 50.0f)) * 50.0f;
    }
    __syncthreads();

    if (t < CHUNKQ) {
        float m = -1e30f;
#pragma unroll
        for (int j = 0; j < CTXQ; j++) m = fmaxf(m, slog[t][j]);
        float s = 0.f;
#pragma unroll
        for (int j = 0; j < CTXQ; j++) {
            float e = __expf(slog[t][j] - m);
            slog[t][j] = e;
            s += e;
        }
        float inv = 1.0f / s;
#pragma unroll
        for (int j = 0; j < CTXQ; j++) slog[t][j] *= inv;
    }
    __syncthreads();

    {
        const int d = t;
#pragma unroll
        for (int i = 0; i < CHUNKQ; i++) {
            float a0 = 0.f, a1 = 0.f;
#pragma unroll
            for (int j = 0; j < CTXQ; j += 2) {
                a0 = fmaf(slog[i][j],     sv[j][d],     a0);
                a1 = fmaf(slog[i][j + 1], sv[j + 1][d], a1);
            }
            int srow = n * CHUNKQ + i;
            if (srow < SEQ)
                g_aoh[base + (size_t)srow * HS + d] = __float2half(a0 + a1);
        }
    }
}

// ---------------- launch ----------------
extern "C" void kernel_launch(void* const* d_in, const int* in_sizes, int n_in,
                              void* d_out, int out_size)
{
    const float* x     = (const float*)d_in[0];
    const float* pe    = (const float*)d_in[1];
    const float* Wq    = (const float*)d_in[2];
    const float* Wk    = (const float*)d_in[3];
    const float* Wv    = (const float*)d_in[4];
    const float* Wpost = (const float*)d_in[5];
    const float* Wrel  = (const float*)d_in[6];
    const float* pds   = (const float*)d_in[7];
    float* out = (float*)d_out;

    prep_xh<<<(size_t)MROWS * HS / 4 / 256, 256>>>(x);
    prep_wh<<<dim3(32, 32, 4), dim3(32, 8)>>>(Wq, Wk, Wv, Wpost);

    dim3 gq(HS / BN, MROWS / BM, 4);     // z=3 slice computes rel_k
    qkv_gemm<<<gq, 256>>>(pds, pe, Wrel);

    attn_kernel<<<BATCH * NBLK * NH, 128>>>();

    dim3 gp(HS / BN, MROWS / BM);
    post_gemm<<<gp, 256>>>(out);
}

// round 5
// speedup vs baseline: 5.3278x; 1.2242x over previous
#include <cuda_runtime.h>
#include <cuda_fp16.h>
#include <math.h>

// ---------------- problem constants ----------------
#define HS    1024
#define NH    8
#define HD    128
#define BATCH 16
#define SEQ   2400
#define NBLK  200
#define MROWS (BATCH*SEQ)          // 38400

#define CHUNKQ 12
#define PASTQ  12
#define CTXQ   24
#define PQ     25

#define Q_SCALE_F (0.08838834764831845f / 0.6931471805599453f)
#define K_SCALE_F (1.3132616875182228f / 0.6931471805599453f)

// ---------------- scratch ----------------
__device__ __half g_qh [(size_t)MROWS * HS];
__device__ __half g_kh [(size_t)MROWS * HS];
__device__ __half g_vh [(size_t)MROWS * HS];
__device__ __half g_aoh[(size_t)MROWS * HS];     // attn out (half)
__device__ __half g_xh [(size_t)MROWS * HS];     // x (half)
__device__ __half g_wth[4][(size_t)HS * HS];     // W^T (half): q,k,v,post
__device__ float  g_relk[PQ * HS];

__device__ __forceinline__ unsigned cvta_smem(const void* p) {
    return (unsigned)__cvta_generic_to_shared(p);
}
__device__ __forceinline__ void cp_async16(void* dst, const void* src) {
    asm volatile("cp.async.cg.shared.global [%0], [%1], 16;\n"
                 :: "r"(cvta_smem(dst)), "l"(src));
}
__device__ __forceinline__ void cp_commit() {
    asm volatile("cp.async.commit_group;\n");
}
__device__ __forceinline__ void ldm_x4(unsigned& r0, unsigned& r1,
                                       unsigned& r2, unsigned& r3, unsigned a) {
    asm volatile("ldmatrix.sync.aligned.m8n8.x4.shared.b16 {%0,%1,%2,%3}, [%4];\n"
                 : "=r"(r0), "=r"(r1), "=r"(r2), "=r"(r3) : "r"(a));
}
__device__ __forceinline__ void ldm_x2(unsigned& r0, unsigned& r1, unsigned a) {
    asm volatile("ldmatrix.sync.aligned.m8n8.x2.shared.b16 {%0,%1}, [%2];\n"
                 : "=r"(r0), "=r"(r1) : "r"(a));
}
__device__ __forceinline__ void mma16816(float* d, unsigned a0, unsigned a1,
                                         unsigned a2, unsigned a3,
                                         unsigned b0, unsigned b1) {
    asm volatile(
        "mma.sync.aligned.m16n8k16.row.col.f32.f16.f16.f32 "
        "{%0,%1,%2,%3}, {%4,%5,%6,%7}, {%8,%9}, {%0,%1,%2,%3};\n"
        : "+f"(d[0]), "+f"(d[1]), "+f"(d[2]), "+f"(d[3])
        : "r"(a0), "r"(a1), "r"(a2), "r"(a3), "r"(b0), "r"(b1));
}

// ---------------- prep ----------------
__global__ __launch_bounds__(256) void prep_xh(const float* __restrict__ x)
{
    if (blockIdx.x < 100) g_relk[blockIdx.x * 256 + threadIdx.x] = 0.f;
    size_t i = ((size_t)blockIdx.x * 256 + threadIdx.x) * 4;
    float4 v = *(const float4*)(x + i);
    *(__half2*)(g_xh + i)     = __floats2half2_rn(v.x, v.y);
    *(__half2*)(g_xh + i + 2) = __floats2half2_rn(v.z, v.w);
}

__global__ __launch_bounds__(256) void prep_wh(
    const float* __restrict__ Wq, const float* __restrict__ Wk,
    const float* __restrict__ Wv, const float* __restrict__ Wpost)
{
    __shared__ float tile[32][33];
    const float* src = (blockIdx.z == 0) ? Wq : (blockIdx.z == 1) ? Wk
                     : (blockIdx.z == 2) ? Wv : Wpost;
    const int tx = threadIdx.x, ty = threadIdx.y;
    const int x0 = blockIdx.x * 32, y0 = blockIdx.y * 32;
#pragma unroll
    for (int i = 0; i < 32; i += 8)
        tile[ty + i][tx] = src[(size_t)(y0 + ty + i) * HS + x0 + tx];
    __syncthreads();
    __half* dst = g_wth[blockIdx.z];
#pragma unroll
    for (int i = 0; i < 32; i += 8)
        dst[(size_t)(x0 + ty + i) * HS + y0 + tx] = __float2half(tile[tx][ty + i]);
}

// ---------------- fp16 tensor-core GEMM ----------------
#define BM 128
#define BN 128
#define BKH 32
#define BKP 40
#define KTILES (HS / BKH)
#define SMEM_GEMM_BYTES (2 * 2 * 128 * BKP * 2)

__device__ __forceinline__ void gemm_fp16(
    const __half* __restrict__ A, const __half* __restrict__ Wt,
    void* __restrict__ Cv, int outHalf,
    int scalemode, const float* __restrict__ pds, float cscale, void* pool)
{
    __half* As = (__half*)pool;
    __half* Bs = As + 2 * 128 * BKP;

    const int t    = threadIdx.x;
    const int lane = t & 31;
    const int warp = t >> 5;
    const int wrow = (warp & 1) * 64;
    const int wcol = (warp >> 1) * 32;
    const int g    = lane >> 2;
    const int tg   = lane & 3;

    const int m0 = blockIdx.y * BM;
    const int n0 = blockIdx.x * BN;

    const int r0c = t >> 2,         c0c = (t & 3) * 8;
    const int r1c = (t + 256) >> 2, c1c = c0c;

    const __half* Abase = A  + (size_t)m0 * HS;
    const __half* Bbase = Wt + (size_t)n0 * HS;

    const int aRow = (lane & 7) + ((lane >> 3) & 1) * 8;
    const int aCol = ((lane >> 4) & 1) * 8;
    const int bRow = (lane & 7) + ((lane >> 4) & 1) * 8;
    const int bCol = ((lane >> 3) & 1) * 8;

    float acc[4][4][4];
#pragma unroll
    for (int i = 0; i < 4; i++)
#pragma unroll
        for (int j = 0; j < 4; j++)
#pragma unroll
            for (int c = 0; c < 4; c++) acc[i][j][c] = 0.f;

    cp_async16(As + (size_t)r0c * BKP + c0c, Abase + (size_t)r0c * HS + c0c);
    cp_async16(As + (size_t)r1c * BKP + c1c, Abase + (size_t)r1c * HS + c1c);
    cp_async16(Bs + (size_t)r0c * BKP + c0c, Bbase + (size_t)r0c * HS + c0c);
    cp_async16(Bs + (size_t)r1c * BKP + c1c, Bbase + (size_t)r1c * HS + c1c);
    cp_commit();

    for (int tile = 0; tile < KTILES; ++tile) {
        const int buf = tile & 1;
        const int bo  = buf * 128 * BKP;
        if (tile + 1 < KTILES) {
            const int nb = (buf ^ 1) * 128 * BKP;
            const int k0 = (tile + 1) * BKH;
            const __half* ap = Abase + k0;
            const __half* bp = Bbase + k0;
            cp_async16(As + nb + (size_t)r0c * BKP + c0c, ap + (size_t)r0c * HS + c0c);
            cp_async16(As + nb + (size_t)r1c * BKP + c1c, ap + (size_t)r1c * HS + c1c);
            cp_async16(Bs + nb + (size_t)r0c * BKP + c0c, bp + (size_t)r0c * HS + c0c);
            cp_async16(Bs + nb + (size_t)r1c * BKP + c1c, bp + (size_t)r1c * HS + c1c);
            cp_commit();
            asm volatile("cp.async.wait_group 1;\n");
        } else {
            asm volatile("cp.async.wait_group 0;\n");
        }
        __syncthreads();

#pragma unroll
        for (int kk = 0; kk < 2; kk++) {
            const int kh = kk * 16;
            unsigned af[4][4], bf[4][2];
#pragma unroll
            for (int mt = 0; mt < 4; mt++) {
                unsigned a = cvta_smem(As + bo +
                    (size_t)(wrow + mt * 16 + aRow) * BKP + kh + aCol);
                ldm_x4(af[mt][0], af[mt][1], af[mt][2], af[mt][3], a);
            }
#pragma unroll
            for (int p = 0; p < 2; p++) {
                unsigned a = cvta_smem(Bs + bo +
                    (size_t)(wcol + p * 16 + bRow) * BKP + kh + bCol);
                ldm_x4(bf[2*p][0], bf[2*p][1], bf[2*p+1][0], bf[2*p+1][1], a);
            }
#pragma unroll
            for (int mt = 0; mt < 4; mt++)
#pragma unroll
                for (int nt = 0; nt < 4; nt++)
                    mma16816(acc[mt][nt], af[mt][0], af[mt][1], af[mt][2],
                             af[mt][3], bf[nt][0], bf[nt][1]);
        }
        __syncthreads();
    }

    float sc[4][2];
#pragma unroll
    for (int nt = 0; nt < 4; nt++) {
#pragma unroll
        for (int ci = 0; ci < 2; ci++) {
            int col = n0 + wcol + nt * 8 + tg * 2 + ci;
            if (scalemode == 1) {
                float p  = pds[col & (HD - 1)];
                float sp = (p > 15.f) ? p : log1pf(expf(p));
                sc[nt][ci] = Q_SCALE_F * sp;
            } else {
                sc[nt][ci] = cscale;
            }
        }
    }
#pragma unroll
    for (int mt = 0; mt < 4; mt++) {
#pragma unroll
        for (int hf = 0; hf < 2; hf++) {
            int row = m0 + wrow + mt * 16 + hf * 8 + g;
#pragma unroll
            for (int nt = 0; nt < 4; nt++) {
                float vx = acc[mt][nt][hf * 2 + 0] * sc[nt][0];
                float vy = acc[mt][nt][hf * 2 + 1] * sc[nt][1];
                size_t off = (size_t)row * HS + n0 + wcol + nt * 8 + tg * 2;
                if (outHalf) {
                    *(__half2*)((__half*)Cv + off) = __floats2half2_rn(vx, vy);
                } else {
                    float2 v; v.x = vx; v.y = vy;
                    *(float2*)((float*)Cv + off) = v;
                }
            }
        }
    }
}

// relk partial (z==3 slice of qkv_gemm)
__device__ __forceinline__ void relk_body(
    const float* __restrict__ pe, const float* __restrict__ Wrel, void* pool)
{
    float* spe = (float*)pool;
    const int t = threadIdx.x;
    const int col = blockIdx.x * 128 + (t & 127);
    const int k0  = blockIdx.y * 256;
    const int kh  = (t >> 7) * 128;

    for (int f = t; f < PQ * 256; f += 256)
        spe[f] = pe[(f >> 8) * HS + k0 + (f & 255)];
    __syncthreads();

    float acc[PQ];
#pragma unroll
    for (int p = 0; p < PQ; p++) acc[p] = 0.f;
    for (int kk = 0; kk < 128; kk++) {
        float w = Wrel[(size_t)(k0 + kh + kk) * HS + col];
#pragma unroll
        for (int p = 0; p < PQ; p++) acc[p] = fmaf(spe[p * 256 + kh + kk], w, acc[p]);
    }
#pragma unroll
    for (int p = 0; p < PQ; p++) atomicAdd(&g_relk[p * HS + col], acc[p]);
}

__global__ __launch_bounds__(256, 2) void qkv_gemm(
    const float* __restrict__ pds,
    const float* __restrict__ pe, const float* __restrict__ Wrel)
{
    __shared__ __align__(16) unsigned char pool[SMEM_GEMM_BYTES];
    int z = blockIdx.z;
    if (z == 3) {
        if (blockIdx.y < 4 && blockIdx.x < 8) relk_body(pe, Wrel, pool);
        return;
    }
    if (z == 0)      gemm_fp16(g_xh, g_wth[0], g_qh, 1, 1, pds,  1.f, pool);
    else if (z == 1) gemm_fp16(g_xh, g_wth[1], g_kh, 1, 0, 0, K_SCALE_F, pool);
    else             gemm_fp16(g_xh, g_wth[2], g_vh, 1, 0, 0, 1.f, pool);
}

__global__ __launch_bounds__(256, 2) void post_gemm(float* __restrict__ out)
{
    __shared__ __align__(16) unsigned char pool[SMEM_GEMM_BYTES];
    gemm_fp16(g_aoh, g_wth[3], out, 0, 0, 0, 1.f, pool);
}

// ---------------- tensor-core blocked local attention ----------------
#define QPITCH 136
#define KPITCH 136
#define VPITCH 40
#define PPITCH 40

__global__ __launch_bounds__(128) void attn_kernel()
{
    __shared__ __half qs [16 * QPITCH];
    __shared__ __half ks [32 * KPITCH];
    __shared__ __half rs [32 * KPITCH];
    __shared__ __half vst[128 * VPITCH];   // transposed V: [d][j]
    __shared__ __half ps [16 * PPITCH];    // probabilities
    __shared__ float  slog[16 * 32];
    __shared__ float  sbd [16 * 32];

    const int bid = blockIdx.x;
    const int h = bid & 7;
    const int n = (bid >> 3) % NBLK;
    const int b = bid / (8 * NBLK);
    const int t = threadIdx.x;
    const int lane = t & 31;
    const int warp = t >> 5;
    const int g    = lane >> 2;
    const int tg   = lane & 3;

    const size_t base = (size_t)b * SEQ * HS + (size_t)h * HD;

    // zero the padded operand tiles
    {
        int4 z = make_int4(0, 0, 0, 0);
        int4* q4 = (int4*)qs;  for (int f = t; f < 16*QPITCH/8;  f += 128) q4[f] = z;
        int4* k4 = (int4*)ks;  for (int f = t; f < 32*KPITCH/8;  f += 128) k4[f] = z;
        int4* r4 = (int4*)rs;  for (int f = t; f < 32*KPITCH/8;  f += 128) r4[f] = z;
        int4* v4 = (int4*)vst; for (int f = t; f < 128*VPITCH/8; f += 128) v4[f] = z;
        int4* p4 = (int4*)ps;  for (int f = t; f < 16*PPITCH/8;  f += 128) p4[f] = z;
    }
    __syncthreads();

    // fill q
    for (int f = t; f < CHUNKQ * 16; f += 128) {
        int i = f >> 4, c = (f & 15) << 3;
        *(int4*)&qs[i * QPITCH + c] =
            *(const int4*)&g_qh[base + (size_t)(n * CHUNKQ + i) * HS + c];
    }
    // fill k and transposed v
    for (int f = t; f < CTXQ * 16; f += 128) {
        int j = f >> 4, c = (f & 15) << 3;
        int s = n * CHUNKQ - PASTQ + j;
        int4 kv = make_int4(0, 0, 0, 0);
        int4 vv = make_int4(0, 0, 0, 0);
        if (s >= 0) {
            kv = *(const int4*)&g_kh[base + (size_t)s * HS + c];
            vv = *(const int4*)&g_vh[base + (size_t)s * HS + c];
        }
        *(int4*)&ks[j * KPITCH + c] = kv;
        __half th[8];
        *(int4*)th = vv;
#pragma unroll
        for (int u = 0; u < 8; u++) vst[(c + u) * VPITCH + j] = th[u];
    }
    // fill rel (fp32 -> half)
    for (int f = t; f < PQ * 32; f += 128) {
        int p = f >> 5, c = (f & 31) << 2;
        float4 r = *(const float4*)&g_relk[(size_t)p * HS + (size_t)h * HD + c];
        rs[p * KPITCH + c + 0] = __float2half(r.x);
        rs[p * KPITCH + c + 1] = __float2half(r.y);
        rs[p * KPITCH + c + 2] = __float2half(r.z);
        rs[p * KPITCH + c + 3] = __float2half(r.w);
    }
    __syncthreads();

    const int aRow = (lane & 7) + ((lane >> 3) & 1) * 8;
    const int aCol = ((lane >> 4) & 1) * 8;
    const int bR   = lane & 7;
    const int bSel = ((lane >> 3) & 1) * 8;

    // score mma: ac (warps 0-2, j-tile 8w) and bd (all warps, p-tile 8w)
    {
        float cac[4] = {0.f, 0.f, 0.f, 0.f};
        float cbd[4] = {0.f, 0.f, 0.f, 0.f};
#pragma unroll
        for (int kh = 0; kh < HD; kh += 16) {
            unsigned a0, a1, a2, a3;
            ldm_x4(a0, a1, a2, a3, cvta_smem(&qs[aRow * QPITCH + kh + aCol]));
            unsigned r0, r1;
            ldm_x2(r0, r1, cvta_smem(&rs[(8 * warp + bR) * KPITCH + kh + bSel]));
            mma16816(cbd, a0, a1, a2, a3, r0, r1);
            if (warp < 3) {
                unsigned k0, k1;
                ldm_x2(k0, k1, cvta_smem(&ks[(8 * warp + bR) * KPITCH + kh + bSel]));
                mma16816(cac, a0, a1, a2, a3, k0, k1);
            }
        }
        int c0 = 8 * warp + 2 * tg;
        if (warp < 3) {
            slog[g * 32 + c0]           = cac[0];
            slog[g * 32 + c0 + 1]       = cac[1];
            slog[(g + 8) * 32 + c0]     = cac[2];
            slog[(g + 8) * 32 + c0 + 1] = cac[3];
        }
        sbd[g * 32 + c0]           = cbd[0];
        sbd[g * 32 + c0 + 1]       = cbd[1];
        sbd[(g + 8) * 32 + c0]     = cbd[2];
        sbd[(g + 8) * 32 + c0 + 1] = cbd[3];
    }
    __syncthreads();

    // rel-shift + softcap
    for (int e = t; e < CHUNKQ * CTXQ; e += 128) {
        int i = e / CTXQ, j = e % CTXQ;
        float val = slog[i * 32 + j] + sbd[(e / PQ) * 32 + (e % PQ)];
        slog[i * 32 + j] = tanhf(val * (1.0f / 50.0f)) * 50.0f;
    }
    __syncthreads();

    // softmax + write P (half)
    if (t < CHUNKQ) {
        float m = -1e30f;
#pragma unroll
        for (int j = 0; j < CTXQ; j++) m = fmaxf(m, slog[t * 32 + j]);
        float s = 0.f;
        float e_[CTXQ];
#pragma unroll
        for (int j = 0; j < CTXQ; j++) {
            e_[j] = __expf(slog[t * 32 + j] - m);
            s += e_[j];
        }
        float inv = 1.0f / s;
#pragma unroll
        for (int j = 0; j < CTXQ; j++)
            ps[t * PPITCH + j] = __float2half(e_[j] * inv);
    }
    __syncthreads();

    // out = P @ V : each warp covers 32 output dims
    {
        unsigned qa[8];
        ldm_x4(qa[0], qa[1], qa[2], qa[3], cvta_smem(&ps[aRow * PPITCH + aCol]));
        ldm_x4(qa[4], qa[5], qa[6], qa[7], cvta_smem(&ps[aRow * PPITCH + 16 + aCol]));
#pragma unroll
        for (int nt = 0; nt < 4; nt++) {
            int n0 = 32 * warp + 8 * nt;
            float co[4] = {0.f, 0.f, 0.f, 0.f};
            unsigned v0, v1;
            ldm_x2(v0, v1, cvta_smem(&vst[(n0 + bR) * VPITCH + bSel]));
            mma16816(co, qa[0], qa[1], qa[2], qa[3], v0, v1);
            ldm_x2(v0, v1, cvta_smem(&vst[(n0 + bR) * VPITCH + 16 + bSel]));
            mma16816(co, qa[4], qa[5], qa[6], qa[7], v0, v1);

            int d0 = n0 + 2 * tg;
            *(__half2*)&g_aoh[base + (size_t)(n * CHUNKQ + g) * HS + d0] =
                __floats2half2_rn(co[0], co[1]);
            if (g < 4)
                *(__half2*)&g_aoh[base + (size_t)(n * CHUNKQ + g + 8) * HS + d0] =
                    __floats2half2_rn(co[2], co[3]);
        }
    }
}

// ---------------- launch ----------------
extern "C" void kernel_launch(void* const* d_in, const int* in_sizes, int n_in,
                              void* d_out, int out_size)
{
    const float* x     = (const float*)d_in[0];
    const float* pe    = (const float*)d_in[1];
    const float* Wq    = (const float*)d_in[2];
    const float* Wk    = (const float*)d_in[3];
    const float* Wv    = (const float*)d_in[4];
    const float* Wpost = (const float*)d_in[5];
    const float* Wrel  = (const float*)d_in[6];
    const float* pds   = (const float*)d_in[7];
    float* out = (float*)d_out;

    prep_xh<<<(size_t)MROWS * HS / 4 / 256, 256>>>(x);
    prep_wh<<<dim3(32, 32, 4), dim3(32, 8)>>>(Wq, Wk, Wv, Wpost);

    dim3 gq(HS / BN, MROWS / BM, 4);
    qkv_gemm<<<gq, 256>>>(pds, pe, Wrel);

    attn_kernel<<<BATCH * NBLK * NH, 128>>>();

    dim3 gp(HS / BN, MROWS / BM);
    post_gemm<<<gp, 256>>>(out);
}

// round 6
// speedup vs baseline: 5.8354x; 1.0953x over previous
#include <cuda_runtime.h>
#include <cuda_fp16.h>
#include <math.h>

// ---------------- problem constants ----------------
#define HS    1024
#define NH    8
#define HD    128
#define BATCH 16
#define SEQ   2400
#define NBLK  200
#define MROWS (BATCH*SEQ)          // 38400

#define CHUNKQ 12
#define PASTQ  12
#define CTXQ   24
#define PQ     25

#define Q_SCALE_F (0.08838834764831845f / 0.6931471805599453f)
#define K_SCALE_F (1.3132616875182228f / 0.6931471805599453f)

// ---------------- scratch ----------------
__device__ __half g_qh [(size_t)MROWS * HS];
__device__ __half g_kh [(size_t)MROWS * HS];
__device__ __half g_vh [(size_t)MROWS * HS];
__device__ __half g_aoh[(size_t)MROWS * HS];
__device__ __half g_xh [(size_t)MROWS * HS];
__device__ __half g_wth[4][(size_t)HS * HS];
__device__ float  g_relk[PQ * HS];

__device__ __forceinline__ unsigned cvta_smem(const void* p) {
    return (unsigned)__cvta_generic_to_shared(p);
}
__device__ __forceinline__ void cp_async16(void* dst, const void* src) {
    asm volatile("cp.async.cg.shared.global [%0], [%1], 16;\n"
                 :: "r"(cvta_smem(dst)), "l"(src));
}
__device__ __forceinline__ void cp_commit() {
    asm volatile("cp.async.commit_group;\n");
}
__device__ __forceinline__ void ldm_x4(unsigned& r0, unsigned& r1,
                                       unsigned& r2, unsigned& r3, unsigned a) {
    asm volatile("ldmatrix.sync.aligned.m8n8.x4.shared.b16 {%0,%1,%2,%3}, [%4];\n"
                 : "=r"(r0), "=r"(r1), "=r"(r2), "=r"(r3) : "r"(a));
}
__device__ __forceinline__ void ldm_x2(unsigned& r0, unsigned& r1, unsigned a) {
    asm volatile("ldmatrix.sync.aligned.m8n8.x2.shared.b16 {%0,%1}, [%2];\n"
                 : "=r"(r0), "=r"(r1) : "r"(a));
}
__device__ __forceinline__ void ldm_x2_trans(unsigned& r0, unsigned& r1, unsigned a) {
    asm volatile("ldmatrix.sync.aligned.m8n8.x2.trans.shared.b16 {%0,%1}, [%2];\n"
                 : "=r"(r0), "=r"(r1) : "r"(a));
}
__device__ __forceinline__ void mma16816(float* d, unsigned a0, unsigned a1,
                                         unsigned a2, unsigned a3,
                                         unsigned b0, unsigned b1) {
    asm volatile(
        "mma.sync.aligned.m16n8k16.row.col.f32.f16.f16.f32 "
        "{%0,%1,%2,%3}, {%4,%5,%6,%7}, {%8,%9}, {%0,%1,%2,%3};\n"
        : "+f"(d[0]), "+f"(d[1]), "+f"(d[2]), "+f"(d[3])
        : "r"(a0), "r"(a1), "r"(a2), "r"(a3), "r"(b0), "r"(b1));
}

// ---------------- prep ----------------
__global__ __launch_bounds__(256) void prep_xh(const float* __restrict__ x)
{
    if (blockIdx.x < 100) g_relk[blockIdx.x * 256 + threadIdx.x] = 0.f;
    size_t i = ((size_t)blockIdx.x * 256 + threadIdx.x) * 4;
    float4 v = *(const float4*)(x + i);
    *(__half2*)(g_xh + i)     = __floats2half2_rn(v.x, v.y);
    *(__half2*)(g_xh + i + 2) = __floats2half2_rn(v.z, v.w);
}

__global__ __launch_bounds__(256) void prep_wh(
    const float* __restrict__ Wq, const float* __restrict__ Wk,
    const float* __restrict__ Wv, const float* __restrict__ Wpost)
{
    __shared__ float tile[32][33];
    const float* src = (blockIdx.z == 0) ? Wq : (blockIdx.z == 1) ? Wk
                     : (blockIdx.z == 2) ? Wv : Wpost;
    const int tx = threadIdx.x, ty = threadIdx.y;
    const int x0 = blockIdx.x * 32, y0 = blockIdx.y * 32;
#pragma unroll
    for (int i = 0; i < 32; i += 8)
        tile[ty + i][tx] = src[(size_t)(y0 + ty + i) * HS + x0 + tx];
    __syncthreads();
    __half* dst = g_wth[blockIdx.z];
#pragma unroll
    for (int i = 0; i < 32; i += 8)
        dst[(size_t)(x0 + ty + i) * HS + y0 + tx] = __float2half(tile[tx][ty + i]);
}

// ---------------- fp16 tensor-core GEMM ----------------
#define BM 128
#define BN 128
#define BKH 32
#define BKP 40
#define KTILES (HS / BKH)
#define SMEM_GEMM_BYTES (2 * 2 * 128 * BKP * 2)

__device__ __forceinline__ void gemm_fp16(
    const __half* __restrict__ A, const __half* __restrict__ Wt,
    void* __restrict__ Cv, int outHalf,
    int scalemode, const float* __restrict__ pds, float cscale, void* pool)
{
    __half* As = (__half*)pool;
    __half* Bs = As + 2 * 128 * BKP;

    const int t    = threadIdx.x;
    const int lane = t & 31;
    const int warp = t >> 5;
    const int wrow = (warp & 1) * 64;
    const int wcol = (warp >> 1) * 32;
    const int g    = lane >> 2;
    const int tg   = lane & 3;

    const int m0 = blockIdx.y * BM;
    const int n0 = blockIdx.x * BN;

    const int r0c = t >> 2,         c0c = (t & 3) * 8;
    const int r1c = (t + 256) >> 2, c1c = c0c;

    const __half* Abase = A  + (size_t)m0 * HS;
    const __half* Bbase = Wt + (size_t)n0 * HS;

    const int aRow = (lane & 7) + ((lane >> 3) & 1) * 8;
    const int aCol = ((lane >> 4) & 1) * 8;
    const int bRow = (lane & 7) + ((lane >> 4) & 1) * 8;
    const int bCol = ((lane >> 3) & 1) * 8;

    float acc[4][4][4];
#pragma unroll
    for (int i = 0; i < 4; i++)
#pragma unroll
        for (int j = 0; j < 4; j++)
#pragma unroll
            for (int c = 0; c < 4; c++) acc[i][j][c] = 0.f;

    cp_async16(As + (size_t)r0c * BKP + c0c, Abase + (size_t)r0c * HS + c0c);
    cp_async16(As + (size_t)r1c * BKP + c1c, Abase + (size_t)r1c * HS + c1c);
    cp_async16(Bs + (size_t)r0c * BKP + c0c, Bbase + (size_t)r0c * HS + c0c);
    cp_async16(Bs + (size_t)r1c * BKP + c1c, Bbase + (size_t)r1c * HS + c1c);
    cp_commit();

    for (int tile = 0; tile < KTILES; ++tile) {
        const int buf = tile & 1;
        const int bo  = buf * 128 * BKP;
        if (tile + 1 < KTILES) {
            const int nb = (buf ^ 1) * 128 * BKP;
            const int k0 = (tile + 1) * BKH;
            const __half* ap = Abase + k0;
            const __half* bp = Bbase + k0;
            cp_async16(As + nb + (size_t)r0c * BKP + c0c, ap + (size_t)r0c * HS + c0c);
            cp_async16(As + nb + (size_t)r1c * BKP + c1c, ap + (size_t)r1c * HS + c1c);
            cp_async16(Bs + nb + (size_t)r0c * BKP + c0c, bp + (size_t)r0c * HS + c0c);
            cp_async16(Bs + nb + (size_t)r1c * BKP + c1c, bp + (size_t)r1c * HS + c1c);
            cp_commit();
            asm volatile("cp.async.wait_group 1;\n");
        } else {
            asm volatile("cp.async.wait_group 0;\n");
        }
        __syncthreads();

#pragma unroll
        for (int kk = 0; kk < 2; kk++) {
            const int kh = kk * 16;
            unsigned af[4][4], bf[4][2];
#pragma unroll
            for (int mt = 0; mt < 4; mt++) {
                unsigned a = cvta_smem(As + bo +
                    (size_t)(wrow + mt * 16 + aRow) * BKP + kh + aCol);
                ldm_x4(af[mt][0], af[mt][1], af[mt][2], af[mt][3], a);
            }
#pragma unroll
            for (int p = 0; p < 2; p++) {
                unsigned a = cvta_smem(Bs + bo +
                    (size_t)(wcol + p * 16 + bRow) * BKP + kh + bCol);
                ldm_x4(bf[2*p][0], bf[2*p][1], bf[2*p+1][0], bf[2*p+1][1], a);
            }
#pragma unroll
            for (int mt = 0; mt < 4; mt++)
#pragma unroll
                for (int nt = 0; nt < 4; nt++)
                    mma16816(acc[mt][nt], af[mt][0], af[mt][1], af[mt][2],
                             af[mt][3], bf[nt][0], bf[nt][1]);
        }
        __syncthreads();
    }

    float sc[4][2];
#pragma unroll
    for (int nt = 0; nt < 4; nt++) {
#pragma unroll
        for (int ci = 0; ci < 2; ci++) {
            int col = n0 + wcol + nt * 8 + tg * 2 + ci;
            if (scalemode == 1) {
                float p  = pds[col & (HD - 1)];
                float sp = (p > 15.f) ? p : log1pf(expf(p));
                sc[nt][ci] = Q_SCALE_F * sp;
            } else {
                sc[nt][ci] = cscale;
            }
        }
    }
#pragma unroll
    for (int mt = 0; mt < 4; mt++) {
#pragma unroll
        for (int hf = 0; hf < 2; hf++) {
            int row = m0 + wrow + mt * 16 + hf * 8 + g;
#pragma unroll
            for (int nt = 0; nt < 4; nt++) {
                float vx = acc[mt][nt][hf * 2 + 0] * sc[nt][0];
                float vy = acc[mt][nt][hf * 2 + 1] * sc[nt][1];
                size_t off = (size_t)row * HS + n0 + wcol + nt * 8 + tg * 2;
                if (outHalf) {
                    *(__half2*)((__half*)Cv + off) = __floats2half2_rn(vx, vy);
                } else {
                    float2 v; v.x = vx; v.y = vy;
                    *(float2*)((float*)Cv + off) = v;
                }
            }
        }
    }
}

// relk partial (z==3 slice of qkv_gemm)
__device__ __forceinline__ void relk_body(
    const float* __restrict__ pe, const float* __restrict__ Wrel, void* pool)
{
    float* spe = (float*)pool;
    const int t = threadIdx.x;
    const int col = blockIdx.x * 128 + (t & 127);
    const int k0  = blockIdx.y * 256;
    const int kh  = (t >> 7) * 128;

    for (int f = t; f < PQ * 256; f += 256)
        spe[f] = pe[(f >> 8) * HS + k0 + (f & 255)];
    __syncthreads();

    float acc[PQ];
#pragma unroll
    for (int p = 0; p < PQ; p++) acc[p] = 0.f;
    for (int kk = 0; kk < 128; kk++) {
        float w = Wrel[(size_t)(k0 + kh + kk) * HS + col];
#pragma unroll
        for (int p = 0; p < PQ; p++) acc[p] = fmaf(spe[p * 256 + kh + kk], w, acc[p]);
    }
#pragma unroll
    for (int p = 0; p < PQ; p++) atomicAdd(&g_relk[p * HS + col], acc[p]);
}

__global__ __launch_bounds__(256, 2) void qkv_gemm(
    const float* __restrict__ pds,
    const float* __restrict__ pe, const float* __restrict__ Wrel)
{
    __shared__ __align__(16) unsigned char pool[SMEM_GEMM_BYTES];
    int z = blockIdx.z;
    if (z == 3) {
        if (blockIdx.y < 4 && blockIdx.x < 8) relk_body(pe, Wrel, pool);
        return;
    }
    if (z == 0)      gemm_fp16(g_xh, g_wth[0], g_qh, 1, 1, pds,  1.f, pool);
    else if (z == 1) gemm_fp16(g_xh, g_wth[1], g_kh, 1, 0, 0, K_SCALE_F, pool);
    else             gemm_fp16(g_xh, g_wth[2], g_vh, 1, 0, 0, 1.f, pool);
}

__global__ __launch_bounds__(256, 2) void post_gemm(float* __restrict__ out)
{
    __shared__ __align__(16) unsigned char pool[SMEM_GEMM_BYTES];
    gemm_fp16(g_aoh, g_wth[3], out, 0, 0, 0, 1.f, pool);
}

// ---------------- tensor-core blocked local attention (v2) ----------------
// No bulk zeroing: garbage only flows to unused outputs; V pad rows zeroed
// (2KB) and P cols 24-31 written as zero in softmax. V consumed via
// ldmatrix.trans (no scalar transpose).
#define QPITCH 136
#define KPITCH 136
#define PPITCH 40

__global__ __launch_bounds__(128) void attn_kernel()
{
    __shared__ __half qs [16 * QPITCH];
    __shared__ __half ks [24 * KPITCH];
    __shared__ __half rs [32 * KPITCH];
    __shared__ __half vs [32 * KPITCH];    // V natural layout [j][d]
    __shared__ __half ps [16 * PPITCH];
    __shared__ float  slog[16 * 32];
    __shared__ float  sbd [16 * 32];

    const int bid = blockIdx.x;
    const int h = bid & 7;
    const int n = (bid >> 3) % NBLK;
    const int b = bid / (8 * NBLK);
    const int t = threadIdx.x;
    const int lane = t & 31;
    const int warp = t >> 5;
    const int g    = lane >> 2;
    const int tg   = lane & 3;

    const size_t base = (size_t)b * SEQ * HS + (size_t)h * HD;

    // q rows 0-11 (rows 12-15 garbage: feed only unused outputs)
    for (int f = t; f < CHUNKQ * 16; f += 128) {
        int i = f >> 4, c = (f & 15) << 3;
        *(int4*)&qs[i * QPITCH + c] =
            *(const int4*)&g_qh[base + (size_t)(n * CHUNKQ + i) * HS + c];
    }
    // k, v rows 0-23 (left-pad rows -> zero)
    for (int f = t; f < CTXQ * 16; f += 128) {
        int j = f >> 4, c = (f & 15) << 3;
        int s = n * CHUNKQ - PASTQ + j;
        int4 kv = make_int4(0, 0, 0, 0);
        int4 vv = make_int4(0, 0, 0, 0);
        if (s >= 0) {
            kv = *(const int4*)&g_kh[base + (size_t)s * HS + c];
            vv = *(const int4*)&g_vh[base + (size_t)s * HS + c];
        }
        *(int4*)&ks[j * KPITCH + c] = kv;
        *(int4*)&vs[j * KPITCH + c] = vv;
    }
    // v pad rows 24-31: MUST be finite (multiplied by zero P cols)
    {
        int4* v4 = (int4*)(vs + 24 * KPITCH);
        int4 z = make_int4(0, 0, 0, 0);
        for (int f = t; f < 8 * KPITCH / 8; f += 128) v4[f] = z;
    }
    // rel rows 0-24 (rows 25-31 garbage: sbd cols 25-31 unused)
    for (int f = t; f < PQ * 32; f += 128) {
        int p = f >> 5, c = (f & 31) << 2;
        float4 r = *(const float4*)&g_relk[(size_t)p * HS + (size_t)h * HD + c];
        __half2 h0 = __floats2half2_rn(r.x, r.y);
        __half2 h1 = __floats2half2_rn(r.z, r.w);
        *(__half2*)&rs[p * KPITCH + c]     = h0;
        *(__half2*)&rs[p * KPITCH + c + 2] = h1;
    }
    __syncthreads();

    const int aRow = (lane & 7) + ((lane >> 3) & 1) * 8;
    const int aCol = ((lane >> 4) & 1) * 8;
    const int bR   = lane & 7;
    const int bSel = ((lane >> 3) & 1) * 8;

    // scores: ac (warps 0-2 over j-tiles) + bd (all warps over p-tiles)
    {
        float cac[4] = {0.f, 0.f, 0.f, 0.f};
        float cbd[4] = {0.f, 0.f, 0.f, 0.f};
#pragma unroll
        for (int kh = 0; kh < HD; kh += 16) {
            unsigned a0, a1, a2, a3;
            ldm_x4(a0, a1, a2, a3, cvta_smem(&qs[aRow * QPITCH + kh + aCol]));
            unsigned r0, r1;
            ldm_x2(r0, r1, cvta_smem(&rs[(8 * warp + bR) * KPITCH + kh + bSel]));
            mma16816(cbd, a0, a1, a2, a3, r0, r1);
            if (warp < 3) {
                unsigned k0, k1;
                ldm_x2(k0, k1, cvta_smem(&ks[(8 * warp + bR) * KPITCH + kh + bSel]));
                mma16816(cac, a0, a1, a2, a3, k0, k1);
            }
        }
        int c0 = 8 * warp + 2 * tg;
        if (warp < 3) {
            slog[g * 32 + c0]           = cac[0];
            slog[g * 32 + c0 + 1]       = cac[1];
            slog[(g + 8) * 32 + c0]     = cac[2];
            slog[(g + 8) * 32 + c0 + 1] = cac[3];
        }
        sbd[g * 32 + c0]           = cbd[0];
        sbd[g * 32 + c0 + 1]       = cbd[1];
        sbd[(g + 8) * 32 + c0]     = cbd[2];
        sbd[(g + 8) * 32 + c0 + 1] = cbd[3];
    }
    __syncthreads();

    // rel-shift + softcap
    for (int e = t; e < CHUNKQ * CTXQ; e += 128) {
        int i = e / CTXQ, j = e % CTXQ;
        float val = slog[i * 32 + j] + sbd[(e / PQ) * 32 + (e % PQ)];
        slog[i * 32 + j] = tanhf(val * (1.0f / 50.0f)) * 50.0f;
    }
    __syncthreads();

    // softmax rows 0-11; write P cols 0-23 + explicit zeros 24-31
    if (t < CHUNKQ) {
        float m = -1e30f;
#pragma unroll
        for (int j = 0; j < CTXQ; j++) m = fmaxf(m, slog[t * 32 + j]);
        float s = 0.f;
        float e_[CTXQ];
#pragma unroll
        for (int j = 0; j < CTXQ; j++) {
            e_[j] = __expf(slog[t * 32 + j] - m);
            s += e_[j];
        }
        float inv = 1.0f / s;
#pragma unroll
        for (int j = 0; j < CTXQ; j += 2)
            *(__half2*)&ps[t * PPITCH + j] =
                __floats2half2_rn(e_[j] * inv, e_[j + 1] * inv);
        __half2 hz = __floats2half2_rn(0.f, 0.f);
#pragma unroll
        for (int j = CTXQ; j < 32; j += 2)
            *(__half2*)&ps[t * PPITCH + j] = hz;
    }
    __syncthreads();

    // out = P @ V via ldmatrix.trans on natural V
    {
        unsigned qa[8];
        ldm_x4(qa[0], qa[1], qa[2], qa[3], cvta_smem(&ps[aRow * PPITCH + aCol]));
        ldm_x4(qa[4], qa[5], qa[6], qa[7], cvta_smem(&ps[aRow * PPITCH + 16 + aCol]));
        const int vr = lane & 15;
#pragma unroll
        for (int nt = 0; nt < 4; nt++) {
            int n0 = 32 * warp + 8 * nt;
            float co[4] = {0.f, 0.f, 0.f, 0.f};
            unsigned v0, v1;
            ldm_x2_trans(v0, v1, cvta_smem(&vs[vr * KPITCH + n0]));
            mma16816(co, qa[0], qa[1], qa[2], qa[3], v0, v1);
            ldm_x2_trans(v0, v1, cvta_smem(&vs[(16 + vr) * KPITCH + n0]));
            mma16816(co, qa[4], qa[5], qa[6], qa[7], v0, v1);

            int d0 = n0 + 2 * tg;
            *(__half2*)&g_aoh[base + (size_t)(n * CHUNKQ + g) * HS + d0] =
                __floats2half2_rn(co[0], co[1]);
            if (g < 4)
                *(__half2*)&g_aoh[base + (size_t)(n * CHUNKQ + g + 8) * HS + d0] =
                    __floats2half2_rn(co[2], co[3]);
        }
    }
}

// ---------------- launch ----------------
extern "C" void kernel_launch(void* const* d_in, const int* in_sizes, int n_in,
                              void* d_out, int out_size)
{
    const float* x     = (const float*)d_in[0];
    const float* pe    = (const float*)d_in[1];
    const float* Wq    = (const float*)d_in[2];
    const float* Wk    = (const float*)d_in[3];
    const float* Wv    = (const float*)d_in[4];
    const float* Wpost = (const float*)d_in[5];
    const float* Wrel  = (const float*)d_in[6];
    const float* pds   = (const float*)d_in[7];
    float* out = (float*)d_out;

    prep_xh<<<(size_t)MROWS * HS / 4 / 256, 256>>>(x);
    prep_wh<<<dim3(32, 32, 4), dim3(32, 8)>>>(Wq, Wk, Wv, Wpost);

    dim3 gq(HS / BN, MROWS / BM, 4);
    qkv_gemm<<<gq, 256>>>(pds, pe, Wrel);

    attn_kernel<<<BATCH * NBLK * NH, 128>>>();

    dim3 gp(HS / BN, MROWS / BM);
    post_gemm<<<gp, 256>>>(out);
}

// round 7
// speedup vs baseline: 6.1258x; 1.0498x over previous
#include <cuda_runtime.h>
#include <cuda_fp16.h>
#include <math.h>

// ---------------- problem constants ----------------
#define HS    1024
#define NH    8
#define HD    128
#define BATCH 16
#define SEQ   2400
#define NBLK  200
#define MROWS (BATCH*SEQ)          // 38400

#define CHUNKQ 12
#define PASTQ  12
#define CTXQ   24
#define PQ     25

#define Q_SCALE_F (0.08838834764831845f / 0.6931471805599453f)
#define K_SCALE_F (1.3132616875182228f / 0.6931471805599453f)

// ---------------- scratch ----------------
__device__ __half g_qh [(size_t)MROWS * HS];
__device__ __half g_kh [(size_t)MROWS * HS];
__device__ __half g_vh [(size_t)MROWS * HS];
__device__ __half g_aoh[(size_t)MROWS * HS];
__device__ __half g_xh [(size_t)MROWS * HS];
__device__ __half g_wth[4][(size_t)HS * HS];
__device__ float  g_relk [PQ * HS];
__device__ __half g_relkh[PQ * HS];

__device__ __forceinline__ unsigned cvta_smem(const void* p) {
    return (unsigned)__cvta_generic_to_shared(p);
}
__device__ __forceinline__ void cp_async16(void* dst, const void* src) {
    asm volatile("cp.async.cg.shared.global [%0], [%1], 16;\n"
                 :: "r"(cvta_smem(dst)), "l"(src));
}
__device__ __forceinline__ void cp_commit() {
    asm volatile("cp.async.commit_group;\n");
}
__device__ __forceinline__ void ldm_x4(unsigned& r0, unsigned& r1,
                                       unsigned& r2, unsigned& r3, unsigned a) {
    asm volatile("ldmatrix.sync.aligned.m8n8.x4.shared.b16 {%0,%1,%2,%3}, [%4];\n"
                 : "=r"(r0), "=r"(r1), "=r"(r2), "=r"(r3) : "r"(a));
}
__device__ __forceinline__ void ldm_x2(unsigned& r0, unsigned& r1, unsigned a) {
    asm volatile("ldmatrix.sync.aligned.m8n8.x2.shared.b16 {%0,%1}, [%2];\n"
                 : "=r"(r0), "=r"(r1) : "r"(a));
}
__device__ __forceinline__ void ldm_x2_trans(unsigned& r0, unsigned& r1, unsigned a) {
    asm volatile("ldmatrix.sync.aligned.m8n8.x2.trans.shared.b16 {%0,%1}, [%2];\n"
                 : "=r"(r0), "=r"(r1) : "r"(a));
}
__device__ __forceinline__ void mma16816(float* d, unsigned a0, unsigned a1,
                                         unsigned a2, unsigned a3,
                                         unsigned b0, unsigned b1) {
    asm volatile(
        "mma.sync.aligned.m16n8k16.row.col.f32.f16.f16.f32 "
        "{%0,%1,%2,%3}, {%4,%5,%6,%7}, {%8,%9}, {%0,%1,%2,%3};\n"
        : "+f"(d[0]), "+f"(d[1]), "+f"(d[2]), "+f"(d[3])
        : "r"(a0), "r"(a1), "r"(a2), "r"(a3), "r"(b0), "r"(b1));
}

// ---------------- prep ----------------
__global__ __launch_bounds__(256) void prep_xh(const float* __restrict__ x)
{
    if (blockIdx.x < 100) g_relk[blockIdx.x * 256 + threadIdx.x] = 0.f;
    size_t i = ((size_t)blockIdx.x * 256 + threadIdx.x) * 4;
    float4 v = *(const float4*)(x + i);
    *(__half2*)(g_xh + i)     = __floats2half2_rn(v.x, v.y);
    *(__half2*)(g_xh + i + 2) = __floats2half2_rn(v.z, v.w);
}

__global__ __launch_bounds__(256) void prep_wh(
    const float* __restrict__ Wq, const float* __restrict__ Wk,
    const float* __restrict__ Wv, const float* __restrict__ Wpost)
{
    __shared__ float tile[32][33];
    const float* src = (blockIdx.z == 0) ? Wq : (blockIdx.z == 1) ? Wk
                     : (blockIdx.z == 2) ? Wv : Wpost;
    const int tx = threadIdx.x, ty = threadIdx.y;
    const int x0 = blockIdx.x * 32, y0 = blockIdx.y * 32;
#pragma unroll
    for (int i = 0; i < 32; i += 8)
        tile[ty + i][tx] = src[(size_t)(y0 + ty + i) * HS + x0 + tx];
    __syncthreads();
    __half* dst = g_wth[blockIdx.z];
#pragma unroll
    for (int i = 0; i < 32; i += 8)
        dst[(size_t)(x0 + ty + i) * HS + y0 + tx] = __float2half(tile[tx][ty + i]);
}

// rel_k fp32 -> half (after relk accumulation)
__global__ __launch_bounds__(256) void relk_half()
{
    int i = blockIdx.x * 256 + threadIdx.x;
    g_relkh[i] = __float2half(g_relk[i]);
}

// ---------------- fp16 tensor-core GEMM (4-stage pipeline) ----------------
#define BM 128
#define BN 128
#define BKH 32
#define BKP 40
#define KTILES (HS / BKH)
#define NSTAGE 4
#define OPSTRIDE (NSTAGE * 128 * BKP)                 // halfs per operand
#define SMEM_DYN (2 * OPSTRIDE * 2)                   // bytes: 81920

extern __shared__ __align__(16) unsigned char dynpool[];

__device__ __forceinline__ void gemm_fp16(
    const __half* __restrict__ A, const __half* __restrict__ Wt,
    void* __restrict__ Cv, int outHalf,
    int scalemode, const float* __restrict__ pds, float cscale)
{
    __half* As = (__half*)dynpool;
    __half* Bs = As + OPSTRIDE;

    const int t    = threadIdx.x;
    const int lane = t & 31;
    const int warp = t >> 5;
    const int wrow = (warp & 1) * 64;
    const int wcol = (warp >> 1) * 32;
    const int g    = lane >> 2;
    const int tg   = lane & 3;

    const int m0 = blockIdx.y * BM;
    const int n0 = blockIdx.x * BN;

    const int r0c = t >> 2,         c0c = (t & 3) * 8;
    const int r1c = (t + 256) >> 2, c1c = c0c;

    const __half* Abase = A  + (size_t)m0 * HS;
    const __half* Bbase = Wt + (size_t)n0 * HS;

    const int aRow = (lane & 7) + ((lane >> 3) & 1) * 8;
    const int aCol = ((lane >> 4) & 1) * 8;
    const int bRow = (lane & 7) + ((lane >> 4) & 1) * 8;
    const int bCol = ((lane >> 3) & 1) * 8;

    float acc[4][4][4];
#pragma unroll
    for (int i = 0; i < 4; i++)
#pragma unroll
        for (int j = 0; j < 4; j++)
#pragma unroll
            for (int c = 0; c < 4; c++) acc[i][j][c] = 0.f;

    // preload NSTAGE-1 tiles
#pragma unroll
    for (int s = 0; s < NSTAGE - 1; s++) {
        const __half* ap = Abase + s * BKH;
        const __half* bp = Bbase + s * BKH;
        __half* Ad = As + s * 128 * BKP;
        __half* Bd = Bs + s * 128 * BKP;
        cp_async16(Ad + (size_t)r0c * BKP + c0c, ap + (size_t)r0c * HS + c0c);
        cp_async16(Ad + (size_t)r1c * BKP + c1c, ap + (size_t)r1c * HS + c1c);
        cp_async16(Bd + (size_t)r0c * BKP + c0c, bp + (size_t)r0c * HS + c0c);
        cp_async16(Bd + (size_t)r1c * BKP + c1c, bp + (size_t)r1c * HS + c1c);
        cp_commit();
    }

    for (int tile = 0; tile < KTILES; ++tile) {
        // wait until tile's group has landed
        {
            int rem = KTILES - 1 - tile;   // groups prefetched beyond this one
            if (rem >= NSTAGE - 2) {
                asm volatile("cp.async.wait_group 2;\n");
            } else if (rem == 1) {
                asm volatile("cp.async.wait_group 1;\n");
            } else if (rem == 0) {
                asm volatile("cp.async.wait_group 0;\n");
            }
        }
        __syncthreads();

        // prefetch tile+NSTAGE-1
        if (tile + NSTAGE - 1 < KTILES) {
            const int s    = tile + NSTAGE - 1;
            const int slot = s & (NSTAGE - 1);
            const __half* ap = Abase + s * BKH;
            const __half* bp = Bbase + s * BKH;
            __half* Ad = As + slot * 128 * BKP;
            __half* Bd = Bs + slot * 128 * BKP;
            cp_async16(Ad + (size_t)r0c * BKP + c0c, ap + (size_t)r0c * HS + c0c);
            cp_async16(Ad + (size_t)r1c * BKP + c1c, ap + (size_t)r1c * HS + c1c);
            cp_async16(Bd + (size_t)r0c * BKP + c0c, bp + (size_t)r0c * HS + c0c);
            cp_async16(Bd + (size_t)r1c * BKP + c1c, bp + (size_t)r1c * HS + c1c);
            cp_commit();
        }

        const int bo = (tile & (NSTAGE - 1)) * 128 * BKP;
#pragma unroll
        for (int kk = 0; kk < 2; kk++) {
            const int kh = kk * 16;
            unsigned af[4][4], bf[4][2];
#pragma unroll
            for (int mt = 0; mt < 4; mt++) {
                unsigned a = cvta_smem(As + bo +
                    (size_t)(wrow + mt * 16 + aRow) * BKP + kh + aCol);
                ldm_x4(af[mt][0], af[mt][1], af[mt][2], af[mt][3], a);
            }
#pragma unroll
            for (int p = 0; p < 2; p++) {
                unsigned a = cvta_smem(Bs + bo +
                    (size_t)(wcol + p * 16 + bRow) * BKP + kh + bCol);
                ldm_x4(bf[2*p][0], bf[2*p][1], bf[2*p+1][0], bf[2*p+1][1], a);
            }
#pragma unroll
            for (int mt = 0; mt < 4; mt++)
#pragma unroll
                for (int nt = 0; nt < 4; nt++)
                    mma16816(acc[mt][nt], af[mt][0], af[mt][1], af[mt][2],
                             af[mt][3], bf[nt][0], bf[nt][1]);
        }
    }

    float sc[4][2];
#pragma unroll
    for (int nt = 0; nt < 4; nt++) {
#pragma unroll
        for (int ci = 0; ci < 2; ci++) {
            int col = n0 + wcol + nt * 8 + tg * 2 + ci;
            if (scalemode == 1) {
                float p  = pds[col & (HD - 1)];
                float sp = (p > 15.f) ? p : log1pf(expf(p));
                sc[nt][ci] = Q_SCALE_F * sp;
            } else {
                sc[nt][ci] = cscale;
            }
        }
    }
#pragma unroll
    for (int mt = 0; mt < 4; mt++) {
#pragma unroll
        for (int hf = 0; hf < 2; hf++) {
            int row = m0 + wrow + mt * 16 + hf * 8 + g;
#pragma unroll
            for (int nt = 0; nt < 4; nt++) {
                float vx = acc[mt][nt][hf * 2 + 0] * sc[nt][0];
                float vy = acc[mt][nt][hf * 2 + 1] * sc[nt][1];
                size_t off = (size_t)row * HS + n0 + wcol + nt * 8 + tg * 2;
                if (outHalf) {
                    *(__half2*)((__half*)Cv + off) = __floats2half2_rn(vx, vy);
                } else {
                    float2 v; v.x = vx; v.y = vy;
                    *(float2*)((float*)Cv + off) = v;
                }
            }
        }
    }
}

// relk partial (z==3 slice of qkv_gemm)
__device__ __forceinline__ void relk_body(
    const float* __restrict__ pe, const float* __restrict__ Wrel)
{
    float* spe = (float*)dynpool;
    const int t = threadIdx.x;
    const int col = blockIdx.x * 128 + (t & 127);
    const int k0  = blockIdx.y * 256;
    const int kh  = (t >> 7) * 128;

    for (int f = t; f < PQ * 256; f += 256)
        spe[f] = pe[(f >> 8) * HS + k0 + (f & 255)];
    __syncthreads();

    float acc[PQ];
#pragma unroll
    for (int p = 0; p < PQ; p++) acc[p] = 0.f;
    for (int kk = 0; kk < 128; kk++) {
        float w = Wrel[(size_t)(k0 + kh + kk) * HS + col];
#pragma unroll
        for (int p = 0; p < PQ; p++) acc[p] = fmaf(spe[p * 256 + kh + kk], w, acc[p]);
    }
#pragma unroll
    for (int p = 0; p < PQ; p++) atomicAdd(&g_relk[p * HS + col], acc[p]);
}

__global__ __launch_bounds__(256, 2) void qkv_gemm(
    const float* __restrict__ pds,
    const float* __restrict__ pe, const float* __restrict__ Wrel)
{
    int z = blockIdx.z;
    if (z == 3) {
        if (blockIdx.y < 4 && blockIdx.x < 8) relk_body(pe, Wrel);
        return;
    }
    if (z == 0)      gemm_fp16(g_xh, g_wth[0], g_qh, 1, 1, pds,  1.f);
    else if (z == 1) gemm_fp16(g_xh, g_wth[1], g_kh, 1, 0, 0, K_SCALE_F);
    else             gemm_fp16(g_xh, g_wth[2], g_vh, 1, 0, 0, 1.f);
}

__global__ __launch_bounds__(256, 2) void post_gemm(float* __restrict__ out)
{
    gemm_fp16(g_aoh, g_wth[3], out, 0, 0, 0, 1.f);
}

// ---------------- tensor-core blocked local attention ----------------
#define QPITCH 136
#define KPITCH 136
#define PPITCH 40

__global__ __launch_bounds__(128) void attn_kernel()
{
    __shared__ __half qs [16 * QPITCH];
    __shared__ __half ks [24 * KPITCH];
    __shared__ __half rs [32 * KPITCH];
    __shared__ __half vs [32 * KPITCH];
    __shared__ __half ps [16 * PPITCH];
    __shared__ float  slog[16 * 32];
    __shared__ float  sbd [16 * 32];

    const int bid = blockIdx.x;
    const int h = bid & 7;
    const int n = (bid >> 3) % NBLK;
    const int b = bid / (8 * NBLK);
    const int t = threadIdx.x;
    const int lane = t & 31;
    const int warp = t >> 5;
    const int g    = lane >> 2;
    const int tg   = lane & 3;

    const size_t base = (size_t)b * SEQ * HS + (size_t)h * HD;

    // q rows 0-11
    for (int f = t; f < CHUNKQ * 16; f += 128) {
        int i = f >> 4, c = (f & 15) << 3;
        *(int4*)&qs[i * QPITCH + c] =
            *(const int4*)&g_qh[base + (size_t)(n * CHUNKQ + i) * HS + c];
    }
    // k, v rows 0-23
    for (int f = t; f < CTXQ * 16; f += 128) {
        int j = f >> 4, c = (f & 15) << 3;
        int s = n * CHUNKQ - PASTQ + j;
        int4 kv = make_int4(0, 0, 0, 0);
        int4 vv = make_int4(0, 0, 0, 0);
        if (s >= 0) {
            kv = *(const int4*)&g_kh[base + (size_t)s * HS + c];
            vv = *(const int4*)&g_vh[base + (size_t)s * HS + c];
        }
        *(int4*)&ks[j * KPITCH + c] = kv;
        *(int4*)&vs[j * KPITCH + c] = vv;
    }
    // v pad rows 24-31 must be finite
    {
        int4* v4 = (int4*)(vs + 24 * KPITCH);
        int4 z = make_int4(0, 0, 0, 0);
        for (int f = t; f < 8 * KPITCH / 8; f += 128) v4[f] = z;
    }
    // rel rows 0-24 (half, precomputed)
    for (int f = t; f < PQ * 16; f += 128) {
        int p = f >> 4, c = (f & 15) << 3;
        *(int4*)&rs[p * KPITCH + c] =
            *(const int4*)&g_relkh[(size_t)p * HS + (size_t)h * HD + c];
    }
    __syncthreads();

    const int aRow = (lane & 7) + ((lane >> 3) & 1) * 8;
    const int aCol = ((lane >> 4) & 1) * 8;
    const int bR   = lane & 7;
    const int bSel = ((lane >> 3) & 1) * 8;

    {
        float cac[4] = {0.f, 0.f, 0.f, 0.f};
        float cbd[4] = {0.f, 0.f, 0.f, 0.f};
#pragma unroll
        for (int kh = 0; kh < HD; kh += 16) {
            unsigned a0, a1, a2, a3;
            ldm_x4(a0, a1, a2, a3, cvta_smem(&qs[aRow * QPITCH + kh + aCol]));
            unsigned r0, r1;
            ldm_x2(r0, r1, cvta_smem(&rs[(8 * warp + bR) * KPITCH + kh + bSel]));
            mma16816(cbd, a0, a1, a2, a3, r0, r1);
            if (warp < 3) {
                unsigned k0, k1;
                ldm_x2(k0, k1, cvta_smem(&ks[(8 * warp + bR) * KPITCH + kh + bSel]));
                mma16816(cac, a0, a1, a2, a3, k0, k1);
            }
        }
        int c0 = 8 * warp + 2 * tg;
        if (warp < 3) {
            slog[g * 32 + c0]           = cac[0];
            slog[g * 32 + c0 + 1]       = cac[1];
            slog[(g + 8) * 32 + c0]     = cac[2];
            slog[(g + 8) * 32 + c0 + 1] = cac[3];
        }
        sbd[g * 32 + c0]           = cbd[0];
        sbd[g * 32 + c0 + 1]       = cbd[1];
        sbd[(g + 8) * 32 + c0]     = cbd[2];
        sbd[(g + 8) * 32 + c0 + 1] = cbd[3];
    }
    __syncthreads();

    for (int e = t; e < CHUNKQ * CTXQ; e += 128) {
        int i = e / CTXQ, j = e % CTXQ;
        float val = slog[i * 32 + j] + sbd[(e / PQ) * 32 + (e % PQ)];
        slog[i * 32 + j] = tanhf(val * (1.0f / 50.0f)) * 50.0f;
    }
    __syncthreads();

    if (t < CHUNKQ) {
        float m = -1e30f;
#pragma unroll
        for (int j = 0; j < CTXQ; j++) m = fmaxf(m, slog[t * 32 + j]);
        float s = 0.f;
        float e_[CTXQ];
#pragma unroll
        for (int j = 0; j < CTXQ; j++) {
            e_[j] = __expf(slog[t * 32 + j] - m);
            s += e_[j];
        }
        float inv = 1.0f / s;
#pragma unroll
        for (int j = 0; j < CTXQ; j += 2)
            *(__half2*)&ps[t * PPITCH + j] =
                __floats2half2_rn(e_[j] * inv, e_[j + 1] * inv);
        __half2 hz = __floats2half2_rn(0.f, 0.f);
#pragma unroll
        for (int j = CTXQ; j < 32; j += 2)
            *(__half2*)&ps[t * PPITCH + j] = hz;
    }
    __syncthreads();

    {
        unsigned qa[8];
        ldm_x4(qa[0], qa[1], qa[2], qa[3], cvta_smem(&ps[aRow * PPITCH + aCol]));
        ldm_x4(qa[4], qa[5], qa[6], qa[7], cvta_smem(&ps[aRow * PPITCH + 16 + aCol]));
        const int vr = lane & 15;
#pragma unroll
        for (int nt = 0; nt < 4; nt++) {
            int n0 = 32 * warp + 8 * nt;
            float co[4] = {0.f, 0.f, 0.f, 0.f};
            unsigned v0, v1;
            ldm_x2_trans(v0, v1, cvta_smem(&vs[vr * KPITCH + n0]));
            mma16816(co, qa[0], qa[1], qa[2], qa[3], v0, v1);
            ldm_x2_trans(v0, v1, cvta_smem(&vs[(16 + vr) * KPITCH + n0]));
            mma16816(co, qa[4], qa[5], qa[6], qa[7], v0, v1);

            int d0 = n0 + 2 * tg;
            *(__half2*)&g_aoh[base + (size_t)(n * CHUNKQ + g) * HS + d0] =
                __floats2half2_rn(co[0], co[1]);
            if (g < 4)
                *(__half2*)&g_aoh[base + (size_t)(n * CHUNKQ + g + 8) * HS + d0] =
                    __floats2half2_rn(co[2], co[3]);
        }
    }
}

// ---------------- launch ----------------
extern "C" void kernel_launch(void* const* d_in, const int* in_sizes, int n_in,
                              void* d_out, int out_size)
{
    const float* x     = (const float*)d_in[0];
    const float* pe    = (const float*)d_in[1];
    const float* Wq    = (const float*)d_in[2];
    const float* Wk    = (const float*)d_in[3];
    const float* Wv    = (const float*)d_in[4];
    const float* Wpost = (const float*)d_in[5];
    const float* Wrel  = (const float*)d_in[6];
    const float* pds   = (const float*)d_in[7];
    float* out = (float*)d_out;

    static int configured = 0;
    if (!configured) {
        cudaFuncSetAttribute(qkv_gemm,
            cudaFuncAttributeMaxDynamicSharedMemorySize, SMEM_DYN);
        cudaFuncSetAttribute(post_gemm,
            cudaFuncAttributeMaxDynamicSharedMemorySize, SMEM_DYN);
        configured = 1;
    }

    prep_xh<<<(size_t)MROWS * HS / 4 / 256, 256>>>(x);
    prep_wh<<<dim3(32, 32, 4), dim3(32, 8)>>>(Wq, Wk, Wv, Wpost);

    dim3 gq(HS / BN, MROWS / BM, 4);
    qkv_gemm<<<gq, 256, SMEM_DYN>>>(pds, pe, Wrel);

    relk_half<<<PQ * HS / 256, 256>>>();

    attn_kernel<<<BATCH * NBLK * NH, 128>>>();

    dim3 gp(HS / BN, MROWS / BM);
    post_gemm<<<gp, 256, SMEM_DYN>>>(out);
}